// round 10
// baseline (speedup 1.0000x reference)
#include <cuda_runtime.h>
#include <cuda_bf16.h>

#define FULL 0xFFFFFFFFu
typedef unsigned long long ull;

// Per-gate Ry part: (cos(theta/2), sin(theta/2)) from ZYZ decomposition
__device__ float2 g_ry[32];
// Diagonal phase tables D0..D3: 4 x 256 complex (cos, sin)
__device__ float2 g_diag[4 * 256];

// Relabeled parity rows per gate (CNOTs folded; must match template R args)
__constant__ int c_rows[32] = {
    0x80,0x40,0x20,0x10,0x08,0x04,0x02,0x01,
    0x80,0xC0,0xE0,0xF0,0xF8,0xFC,0xFE,0xFF,
    0x80,0x40,0xA0,0x50,0xA8,0x54,0xAA,0x55,
    0x80,0xC0,0x60,0x30,0x98,0xCC,0x66,0x33
};

// ---- single fused prep kernel (1024 threads, one block) ----
__global__ void prep(const float* __restrict__ w) {
    __shared__ float s_lam[32], s_phi[32];
    int t = threadIdx.x;
    if (t < 32) {
        int base = t * 3;
        float ta = w[base]     * 0.5f;
        float tb = w[base + 1] * 0.5f;
        float tc = w[base + 2] * 0.5f;
        float sa = sinf(ta), ca = cosf(ta);
        float sb = sinf(tb), cb = cosf(tb);
        float sc = sinf(tc), cc = cosf(tc);
        float m00r = cb * ca, m00i = sb * sa;
        float m01r = -sb * ca, m01i = -cb * sa;
        float x = cc * m00r + sc * m00i;
        float y = cc * m00i - sc * m00r;
        float z = cc * m01r + sc * m01i;
        float q = cc * m01i - sc * m01r;
        float ct = sqrtf(x * x + y * y);
        float st = sqrtf(z * z + q * q);
        float a = -atan2f(y, x);
        float b = atan2f(q, -z);
        g_ry[t] = make_float2(ct, st);
        s_lam[t] = a - b;
        s_phi[t] = a + b;
    }
    __syncthreads();

    int j = t >> 8;
    int s = t & 255;
    float th = 0.f;
#pragma unroll
    for (int g = 0; g < 8; g++) {
        int gg = 8 * j + g;
        float sg = (__popc(c_rows[gg] & s) & 1) ? 1.f : -1.f;
        th += 0.5f * s_lam[gg] * sg;
    }
    if (j > 0) {
#pragma unroll
        for (int g = 0; g < 8; g++) {
            int gg = 8 * (j - 1) + g;
            float sg = (__popc(c_rows[gg] & s) & 1) ? 1.f : -1.f;
            th += 0.5f * s_phi[gg] * sg;
        }
    }
    float sn, cn;
    __sincosf(th, &sn, &cn);
    g_diag[j * 256 + s] = make_float2(cn, sn);
}

// ---- packed fp32x2 helpers: lanes = (sampleA, sampleB) ----
__device__ __forceinline__ ull fma2(ull a, ull b, ull c) {
    ull d; asm("fma.rn.f32x2 %0, %1, %2, %3;" : "=l"(d) : "l"(a), "l"(b), "l"(c));
    return d;
}
__device__ __forceinline__ ull mul2(ull a, ull b) {
    ull d; asm("mul.rn.f32x2 %0, %1, %2;" : "=l"(d) : "l"(a), "l"(b));
    return d;
}
__device__ __forceinline__ ull pack2(float lo, float hi) {
    ull d; asm("mov.b64 %0, {%1, %2};" : "=l"(d) : "f"(lo), "f"(hi));
    return d;
}
__device__ __forceinline__ float lo32(ull v) { return __uint_as_float((unsigned)v); }
__device__ __forceinline__ float hi32(ull v) { return __uint_as_float((unsigned)(v >> 32)); }

// ---- Ry gate, 16-lane layout: lane4 bits = state bits 7..4, k = bits 3..0
// new[s] = c*a[s] + sigma(s)*st*a[s^M], sigma = +1 if <R,s> odd else -1.
// 0x6996 = parity lookup for 4-bit values.
template<int M, int R, int G>
__device__ __forceinline__ void rygate(ull (&vr)[16], ull (&vi)[16], int lane4) {
    const float2 cs = g_ry[G];
    constexpr int ML = (M >> 4) & 15;
    constexpr int MK = M & 15;
    constexpr int RL = (R >> 4) & 15;
    constexpr int RK = R & 15;
    constexpr int HB = (MK >= 8) ? 8 : (MK >= 4) ? 4 : (MK >= 2) ? 2 : 1;

    int pl = (0x6996 >> (lane4 & RL)) & 1;
    float sA = pl ? cs.y : -cs.y;
    ull cc2 = pack2(cs.x, cs.x);
    ull sP  = pack2(sA, sA);
    ull sN  = pack2(-sA, -sA);

    if constexpr (ML != 0 && MK == 0) {
        // cross-lane, same local slot: lockstep shuffle reads old value, safe
#pragma unroll
        for (int k = 0; k < 16; k++) {
            ull br = __shfl_xor_sync(FULL, vr[k], ML);
            ull bi = __shfl_xor_sync(FULL, vi[k], ML);
            ull sk = ((0x6996 >> (RK & k)) & 1) ? sN : sP;  // compile-time select
            vr[k] = fma2(sk, br, mul2(cc2, vr[k]));
            vi[k] = fma2(sk, bi, mul2(cc2, vi[k]));
        }
    } else if constexpr (ML != 0) {
        // mixed: pair-complete — all shuffles of pair (k, k^MK) before any write
#pragma unroll
        for (int k = 0; k < 16; k++) {
            if ((k & HB) == 0) {
                const int k2 = k ^ MK;
                ull pr = __shfl_xor_sync(FULL, vr[k2], ML);
                ull pi = __shfl_xor_sync(FULL, vi[k2], ML);
                ull qr = __shfl_xor_sync(FULL, vr[k],  ML);
                ull qi = __shfl_xor_sync(FULL, vi[k],  ML);
                ull s1 = ((0x6996 >> (RK & k )) & 1) ? sN : sP;
                ull s2 = ((0x6996 >> (RK & k2)) & 1) ? sN : sP;
                vr[k]  = fma2(s1, pr, mul2(cc2, vr[k]));
                vi[k]  = fma2(s1, pi, mul2(cc2, vi[k]));
                vr[k2] = fma2(s2, qr, mul2(cc2, vr[k2]));
                vi[k2] = fma2(s2, qi, mul2(cc2, vi[k2]));
            }
        }
    } else {
        // purely local pairs, in place
#pragma unroll
        for (int k = 0; k < 16; k++) {
            if ((k & HB) == 0) {
                const int k2 = k ^ MK;
                ull s1 = ((0x6996 >> (RK & k )) & 1) ? sN : sP;
                ull s2 = ((0x6996 >> (RK & k2)) & 1) ? sN : sP;
                ull tr = vr[k], ti = vi[k], ur = vr[k2], ui = vi[k2];
                vr[k]  = fma2(s1, ur, mul2(cc2, tr));
                vi[k]  = fma2(s1, ui, mul2(cc2, ti));
                vr[k2] = fma2(s2, tr, mul2(cc2, ur));
                vi[k2] = fma2(s2, ti, mul2(cc2, ui));
            }
        }
    }
}

__device__ __forceinline__ void applyD(ull (&vr)[16], ull (&vi)[16], int lane4, int j) {
    const float4* __restrict__ t = (const float4*)(g_diag + j * 256 + lane4 * 16);
#pragma unroll
    for (int h = 0; h < 8; h++) {
        float4 p = __ldg(&t[h]);    // two slots' phases; serves both samples
        int k = 2 * h;
        {
            ull px = pack2(p.x, p.x), py = pack2(p.y, p.y), pyn = pack2(-p.y, -p.y);
            ull nr = fma2(px, vr[k], mul2(pyn, vi[k]));
            ull ni = fma2(px, vi[k], mul2(py,  vr[k]));
            vr[k] = nr; vi[k] = ni;
        }
        {
            ull px = pack2(p.z, p.z), py = pack2(p.w, p.w), pyn = pack2(-p.w, -p.w);
            ull nr = fma2(px, vr[k+1], mul2(pyn, vi[k+1]));
            ull ni = fma2(px, vi[k+1], mul2(py,  vr[k+1]));
            vr[k+1] = nr; vi[k+1] = ni;
        }
    }
}

__global__ void __launch_bounds__(128, 6)
qsim(const float* __restrict__ x, float* __restrict__ out, int W) {
    int warp = (blockIdx.x * blockDim.x + threadIdx.x) >> 5;  // 0..W-1
    int lane = threadIdx.x & 31;
    if (warp >= W) return;
    int lane4 = lane & 15;    // state bits 7..4 (qubits 0..3)
    int grp = lane >> 4;      // half-warp group: samples (4w+2g, 4w+2g+1)
    int gbase = lane & 16;

    // ---- encoding: 32 lanes load the 32 angles of 4 samples ----
    float xq = x[warp * 32 + lane];
    float sh, ch;
    __sincosf(0.5f * xq, &sh, &ch);

    // lp over qubits 0..3 (lane4 bits 3..0) — consume shuffles immediately
    float lp0 = 1.f, lp1 = 1.f;
#pragma unroll
    for (int q = 0; q < 4; q++) {
        float cA = __shfl_sync(FULL, ch, gbase + q);
        float sA = __shfl_sync(FULL, sh, gbase + q);
        float cB = __shfl_sync(FULL, ch, gbase + 8 + q);
        float sB = __shfl_sync(FULL, sh, gbase + 8 + q);
        bool b = (lane4 >> (3 - q)) & 1;
        lp0 *= b ? sA : cA;
        lp1 *= b ? sB : cB;
    }
    // qubits 4..7 cos/sin kept (k bit (7-q) selects)
    float cq0[4], sq0[4], cq1[4], sq1[4];
#pragma unroll
    for (int q = 0; q < 4; q++) {
        cq0[q] = __shfl_sync(FULL, ch, gbase + 4 + q);
        sq0[q] = __shfl_sync(FULL, sh, gbase + 4 + q);
        cq1[q] = __shfl_sync(FULL, ch, gbase + 12 + q);
        sq1[q] = __shfl_sync(FULL, sh, gbase + 12 + q);
    }

    // init: per-slot amplitude recomputed (4 FMUL), folded with D0 phase
    ull vr[16], vi[16];
    {
        const float4* __restrict__ d0p = (const float4*)(g_diag + lane4 * 16);
#pragma unroll
        for (int h = 0; h < 8; h++) {
            float4 p = __ldg(&d0p[h]);
#pragma unroll
            for (int u = 0; u < 2; u++) {
                int k = 2 * h + u;
                float a0 = lp0 * ((k & 8) ? sq0[0] : cq0[0]) * ((k & 4) ? sq0[1] : cq0[1]) *
                                 ((k & 2) ? sq0[2] : cq0[2]) * ((k & 1) ? sq0[3] : cq0[3]);
                float a1 = lp1 * ((k & 8) ? sq1[0] : cq1[0]) * ((k & 4) ? sq1[1] : cq1[1]) *
                                 ((k & 2) ? sq1[2] : cq1[2]) * ((k & 1) ? sq1[3] : cq1[3]);
                float pr = u ? p.z : p.x;
                float pi = u ? p.w : p.y;
                vr[k] = pack2(a0 * pr, a1 * pr);
                vi[k] = pack2(a0 * pi, a1 * pi);
            }
        }
    }

    // ---- RyBlock layer 1 ----
    rygate<0x80, 0x80,  0>(vr, vi, lane4);
    rygate<0x40, 0x40,  1>(vr, vi, lane4);
    rygate<0x20, 0x20,  2>(vr, vi, lane4);
    rygate<0x10, 0x10,  3>(vr, vi, lane4);
    rygate<0x08, 0x08,  4>(vr, vi, lane4);
    rygate<0x04, 0x04,  5>(vr, vi, lane4);
    rygate<0x02, 0x02,  6>(vr, vi, lane4);
    rygate<0x01, 0x01,  7>(vr, vi, lane4);
    applyD(vr, vi, lane4, 1);
    // ---- layer 2 ----
    rygate<0xC0, 0x80,  8>(vr, vi, lane4);
    rygate<0x60, 0xC0,  9>(vr, vi, lane4);
    rygate<0x30, 0xE0, 10>(vr, vi, lane4);
    rygate<0x18, 0xF0, 11>(vr, vi, lane4);
    rygate<0x0C, 0xF8, 12>(vr, vi, lane4);
    rygate<0x06, 0xFC, 13>(vr, vi, lane4);
    rygate<0x03, 0xFE, 14>(vr, vi, lane4);
    rygate<0x01, 0xFF, 15>(vr, vi, lane4);
    applyD(vr, vi, lane4, 2);
    // ---- layer 3 ----
    rygate<0xA0, 0x80, 16>(vr, vi, lane4);
    rygate<0x50, 0x40, 17>(vr, vi, lane4);
    rygate<0x28, 0xA0, 18>(vr, vi, lane4);
    rygate<0x14, 0x50, 19>(vr, vi, lane4);
    rygate<0x0A, 0xA8, 20>(vr, vi, lane4);
    rygate<0x05, 0x54, 21>(vr, vi, lane4);
    rygate<0x02, 0xAA, 22>(vr, vi, lane4);
    rygate<0x01, 0x55, 23>(vr, vi, lane4);
    applyD(vr, vi, lane4, 3);
    // ---- layer 4 (trailing diagonal dropped: |amp|^2 invariant) ----
    rygate<0xF0, 0x80, 24>(vr, vi, lane4);
    rygate<0x78, 0xC0, 25>(vr, vi, lane4);
    rygate<0x3C, 0x60, 26>(vr, vi, lane4);
    rygate<0x1E, 0x30, 27>(vr, vi, lane4);
    rygate<0x0F, 0x98, 28>(vr, vi, lane4);
    rygate<0x07, 0xCC, 29>(vr, vi, lane4);
    rygate<0x03, 0x66, 30>(vr, vi, lane4);
    rygate<0x01, 0x33, 31>(vr, vi, lane4);

    // ---- measurement: rows q0..q7 = 80,40,20,10,88,44,22,11 ----
    float P0 = 0.f, S80 = 0.f, S40 = 0.f, S20 = 0.f, S10 = 0.f;
    float P1 = 0.f, S81 = 0.f, S41 = 0.f, S21 = 0.f, S11 = 0.f;
#pragma unroll
    for (int k = 0; k < 16; k++) {
        float r0 = lo32(vr[k]), i0 = lo32(vi[k]);
        float r1 = hi32(vr[k]), i1 = hi32(vi[k]);
        float p0 = r0 * r0 + i0 * i0;
        float p1 = r1 * r1 + i1 * i1;
        P0 += p0;                          P1 += p1;
        S80 += (k & 8) ? -p0 : p0;         S81 += (k & 8) ? -p1 : p1;
        S40 += (k & 4) ? -p0 : p0;         S41 += (k & 4) ? -p1 : p1;
        S20 += (k & 2) ? -p0 : p0;         S21 += (k & 2) ? -p1 : p1;
        S10 += (k & 1) ? -p0 : p0;         S11 += (k & 1) ? -p1 : p1;
    }
    float g8 = (lane4 & 8) ? -1.f : 1.f;
    float g4 = (lane4 & 4) ? -1.f : 1.f;
    float g2 = (lane4 & 2) ? -1.f : 1.f;
    float g1 = (lane4 & 1) ? -1.f : 1.f;
    float z[16];
    z[0]  = g8 * P0;   z[1]  = g4 * P0;   z[2]  = g2 * P0;   z[3]  = g1 * P0;
    z[4]  = g8 * S80;  z[5]  = g4 * S40;  z[6]  = g2 * S20;  z[7]  = g1 * S10;
    z[8]  = g8 * P1;   z[9]  = g4 * P1;   z[10] = g2 * P1;   z[11] = g1 * P1;
    z[12] = g8 * S81;  z[13] = g4 * S41;  z[14] = g2 * S21;  z[15] = g1 * S11;

#pragma unroll
    for (int off = 8; off >= 1; off >>= 1) {
#pragma unroll
        for (int i = 0; i < 16; i++)
            z[i] += __shfl_xor_sync(FULL, z[i], off);
    }
    if (lane4 == 0) {
        float4* o = (float4*)(out + warp * 32 + grp * 16);
        o[0] = make_float4(z[0],  z[1],  z[2],  z[3]);
        o[1] = make_float4(z[4],  z[5],  z[6],  z[7]);
        o[2] = make_float4(z[8],  z[9],  z[10], z[11]);
        o[3] = make_float4(z[12], z[13], z[14], z[15]);
    }
}

extern "C" void kernel_launch(void* const* d_in, const int* in_sizes, int n_in,
                              void* d_out, int out_size) {
    const float* x = (const float*)d_in[0];
    const float* w = (const float*)d_in[1];
    float* out = (float*)d_out;
    int B = in_sizes[0] / 8;
    int W = B / 4;   // 4 samples per warp (16-lane groups, f32x2-packed pairs)

    prep<<<1, 1024>>>(w);

    int threads = 128;
    long long total = (long long)W * 32;
    int blocks = (int)((total + threads - 1) / threads);
    qsim<<<blocks, threads>>>(x, out, W);
}

// round 11
// speedup vs baseline: 1.1850x; 1.1850x over previous
#include <cuda_runtime.h>
#include <cuda_bf16.h>

#define FULL 0xFFFFFFFFu
typedef unsigned long long ull;

// Per-gate tangent t = sin(theta/2)/cos(theta/2) from ZYZ decomposition
__device__ float g_t[32];
// Global scale C^2, C = prod of all 32 gate cosines
__device__ float g_C2;
// Diagonal phase tables D0..D3: 4 x 256 complex (cos, sin)
__device__ float2 g_diag[4 * 256];

// Relabeled parity rows per gate (CNOTs folded; must match template R args)
__constant__ int c_rows[32] = {
    0x80,0x40,0x20,0x10,0x08,0x04,0x02,0x01,
    0x80,0xC0,0xE0,0xF0,0xF8,0xFC,0xFE,0xFF,
    0x80,0x40,0xA0,0x50,0xA8,0x54,0xAA,0x55,
    0x80,0xC0,0x60,0x30,0x98,0xCC,0x66,0x33
};

// ---- single fused prep kernel (1024 threads, one block) ----
__global__ void prep(const float* __restrict__ w) {
    __shared__ float s_lam[32], s_phi[32], s_ct[32];
    int t = threadIdx.x;
    if (t < 32) {
        int base = t * 3;
        float ta = w[base]     * 0.5f;
        float tb = w[base + 1] * 0.5f;
        float tc = w[base + 2] * 0.5f;
        float sa = sinf(ta), ca = cosf(ta);
        float sb = sinf(tb), cb = cosf(tb);
        float sc = sinf(tc), cc = cosf(tc);
        float m00r = cb * ca, m00i = sb * sa;
        float m01r = -sb * ca, m01i = -cb * sa;
        float x = cc * m00r + sc * m00i;
        float y = cc * m00i - sc * m00r;
        float z = cc * m01r + sc * m01i;
        float q = cc * m01i - sc * m01r;
        float ct = sqrtf(x * x + y * y);
        float st = sqrtf(z * z + q * q);
        float a = -atan2f(y, x);
        float b = atan2f(q, -z);
        g_t[t] = st / fmaxf(ct, 1e-30f);   // tangent form (ct ~ 1 for small weights)
        s_ct[t] = ct;
        s_lam[t] = a - b;
        s_phi[t] = a + b;
    }
    __syncthreads();
    if (t == 0) {
        float C = 1.f;
#pragma unroll
        for (int g = 0; g < 32; g++) C *= s_ct[g];
        g_C2 = C * C;
    }

    int j = t >> 8;
    int s = t & 255;
    float th = 0.f;
#pragma unroll
    for (int g = 0; g < 8; g++) {
        int gg = 8 * j + g;
        float sg = (__popc(c_rows[gg] & s) & 1) ? 1.f : -1.f;
        th += 0.5f * s_lam[gg] * sg;
    }
    if (j > 0) {
#pragma unroll
        for (int g = 0; g < 8; g++) {
            int gg = 8 * (j - 1) + g;
            float sg = (__popc(c_rows[gg] & s) & 1) ? 1.f : -1.f;
            th += 0.5f * s_phi[gg] * sg;
        }
    }
    float sn, cn;
    __sincosf(th, &sn, &cn);
    g_diag[j * 256 + s] = make_float2(cn, sn);
}

// ---- packed fp32x2 helpers: lanes = (sampleA, sampleB) ----
__device__ __forceinline__ ull fma2(ull a, ull b, ull c) {
    ull d; asm("fma.rn.f32x2 %0, %1, %2, %3;" : "=l"(d) : "l"(a), "l"(b), "l"(c));
    return d;
}
__device__ __forceinline__ ull mul2(ull a, ull b) {
    ull d; asm("mul.rn.f32x2 %0, %1, %2;" : "=l"(d) : "l"(a), "l"(b));
    return d;
}
__device__ __forceinline__ ull pack2(float lo, float hi) {
    ull d; asm("mov.b64 %0, {%1, %2};" : "=l"(d) : "f"(lo), "f"(hi));
    return d;
}
__device__ __forceinline__ float lo32(ull v) { return __uint_as_float((unsigned)v); }
__device__ __forceinline__ float hi32(ull v) { return __uint_as_float((unsigned)(v >> 32)); }

// ---- fast-Givens Ry gate, 16-lane layout: lane4 = state bits 7..4, k = bits 3..0
// new[s] = a[s] + sigma(s)*t*a[s^M]  (global factor c per gate hoisted into g_C2)
// sigma = +1 if <R,s> odd else -1.  0x6996 = 4-bit parity lookup.
template<int M, int R, int G>
__device__ __forceinline__ void rygate(ull (&vr)[16], ull (&vi)[16], int lane4) {
    const float tg = g_t[G];
    constexpr int ML = (M >> 4) & 15;
    constexpr int MK = M & 15;
    constexpr int RL = (R >> 4) & 15;
    constexpr int RK = R & 15;
    constexpr int HB = (MK >= 8) ? 8 : (MK >= 4) ? 4 : (MK >= 2) ? 2 : 1;

    int pl = (0x6996 >> (lane4 & RL)) & 1;
    float tA = pl ? tg : -tg;
    ull tP = pack2(tA, tA);
    ull tN = pack2(-tA, -tA);

    if constexpr (ML != 0 && MK == 0) {
        // cross-lane, same local slot: lockstep shuffle reads old value, safe
#pragma unroll
        for (int k = 0; k < 16; k++) {
            ull br = __shfl_xor_sync(FULL, vr[k], ML);
            ull bi = __shfl_xor_sync(FULL, vi[k], ML);
            ull sk = ((0x6996 >> (RK & k)) & 1) ? tN : tP;  // compile-time select
            vr[k] = fma2(sk, br, vr[k]);
            vi[k] = fma2(sk, bi, vi[k]);
        }
    } else if constexpr (ML != 0) {
        // mixed: pair-complete — all shuffles of pair (k, k^MK) before any write
#pragma unroll
        for (int k = 0; k < 16; k++) {
            if ((k & HB) == 0) {
                const int k2 = k ^ MK;
                ull pr = __shfl_xor_sync(FULL, vr[k2], ML);
                ull pi = __shfl_xor_sync(FULL, vi[k2], ML);
                ull qr = __shfl_xor_sync(FULL, vr[k],  ML);
                ull qi = __shfl_xor_sync(FULL, vi[k],  ML);
                ull s1 = ((0x6996 >> (RK & k )) & 1) ? tN : tP;
                ull s2 = ((0x6996 >> (RK & k2)) & 1) ? tN : tP;
                vr[k]  = fma2(s1, pr, vr[k]);
                vi[k]  = fma2(s1, pi, vi[k]);
                vr[k2] = fma2(s2, qr, vr[k2]);
                vi[k2] = fma2(s2, qi, vi[k2]);
            }
        }
    } else {
        // purely local pairs, in place (save old values of the pair first)
#pragma unroll
        for (int k = 0; k < 16; k++) {
            if ((k & HB) == 0) {
                const int k2 = k ^ MK;
                ull s1 = ((0x6996 >> (RK & k )) & 1) ? tN : tP;
                ull s2 = ((0x6996 >> (RK & k2)) & 1) ? tN : tP;
                ull tr = vr[k], ti = vi[k], ur = vr[k2], ui = vi[k2];
                vr[k]  = fma2(s1, ur, tr);
                vi[k]  = fma2(s1, ui, ti);
                vr[k2] = fma2(s2, tr, ur);
                vi[k2] = fma2(s2, ti, ui);
            }
        }
    }
}

__device__ __forceinline__ void applyD(ull (&vr)[16], ull (&vi)[16], int lane4, int j) {
    const float4* __restrict__ t = (const float4*)(g_diag + j * 256 + lane4 * 16);
#pragma unroll
    for (int h = 0; h < 8; h++) {
        float4 p = __ldg(&t[h]);    // two slots' phases; serves both samples
        int k = 2 * h;
        {
            ull px = pack2(p.x, p.x), py = pack2(p.y, p.y), pyn = pack2(-p.y, -p.y);
            ull nr = fma2(px, vr[k], mul2(pyn, vi[k]));
            ull ni = fma2(px, vi[k], mul2(py,  vr[k]));
            vr[k] = nr; vi[k] = ni;
        }
        {
            ull px = pack2(p.z, p.z), py = pack2(p.w, p.w), pyn = pack2(-p.w, -p.w);
            ull nr = fma2(px, vr[k+1], mul2(pyn, vi[k+1]));
            ull ni = fma2(px, vi[k+1], mul2(py,  vr[k+1]));
            vr[k+1] = nr; vi[k+1] = ni;
        }
    }
}

__global__ void __launch_bounds__(128)
qsim(const float* __restrict__ x, float* __restrict__ out, int W) {
    int warp = (blockIdx.x * blockDim.x + threadIdx.x) >> 5;  // 0..W-1
    int lane = threadIdx.x & 31;
    if (warp >= W) return;
    int lane4 = lane & 15;    // state bits 7..4 (qubits 0..3)
    int grp = lane >> 4;      // half-warp group: samples (4w+2g, 4w+2g+1)
    int gbase = lane & 16;

    // ---- encoding: 32 lanes load the 32 angles of 4 samples ----
    float xq = x[warp * 32 + lane];
    float sh, ch;
    __sincosf(0.5f * xq, &sh, &ch);

    // lp over qubits 0..3 (lane4 bits 3..0) — consume shuffles immediately
    float lp0 = 1.f, lp1 = 1.f;
#pragma unroll
    for (int q = 0; q < 4; q++) {
        float cA = __shfl_sync(FULL, ch, gbase + q);
        float sA = __shfl_sync(FULL, sh, gbase + q);
        float cB = __shfl_sync(FULL, ch, gbase + 8 + q);
        float sB = __shfl_sync(FULL, sh, gbase + 8 + q);
        bool b = (lane4 >> (3 - q)) & 1;
        lp0 *= b ? sA : cA;
        lp1 *= b ? sB : cB;
    }
    // qubits 4..7 cos/sin kept (k bit (7-q) selects)
    float cq0[4], sq0[4], cq1[4], sq1[4];
#pragma unroll
    for (int q = 0; q < 4; q++) {
        cq0[q] = __shfl_sync(FULL, ch, gbase + 4 + q);
        sq0[q] = __shfl_sync(FULL, sh, gbase + 4 + q);
        cq1[q] = __shfl_sync(FULL, ch, gbase + 12 + q);
        sq1[q] = __shfl_sync(FULL, sh, gbase + 12 + q);
    }

    // init: per-slot amplitude recomputed (4 FMUL), folded with D0 phase
    ull vr[16], vi[16];
    {
        const float4* __restrict__ d0p = (const float4*)(g_diag + lane4 * 16);
#pragma unroll
        for (int h = 0; h < 8; h++) {
            float4 p = __ldg(&d0p[h]);
#pragma unroll
            for (int u = 0; u < 2; u++) {
                int k = 2 * h + u;
                float a0 = lp0 * ((k & 8) ? sq0[0] : cq0[0]) * ((k & 4) ? sq0[1] : cq0[1]) *
                                 ((k & 2) ? sq0[2] : cq0[2]) * ((k & 1) ? sq0[3] : cq0[3]);
                float a1 = lp1 * ((k & 8) ? sq1[0] : cq1[0]) * ((k & 4) ? sq1[1] : cq1[1]) *
                                 ((k & 2) ? sq1[2] : cq1[2]) * ((k & 1) ? sq1[3] : cq1[3]);
                float pr = u ? p.z : p.x;
                float pi = u ? p.w : p.y;
                vr[k] = pack2(a0 * pr, a1 * pr);
                vi[k] = pack2(a0 * pi, a1 * pi);
            }
        }
    }

    // ---- RyBlock layer 1 ----
    rygate<0x80, 0x80,  0>(vr, vi, lane4);
    rygate<0x40, 0x40,  1>(vr, vi, lane4);
    rygate<0x20, 0x20,  2>(vr, vi, lane4);
    rygate<0x10, 0x10,  3>(vr, vi, lane4);
    rygate<0x08, 0x08,  4>(vr, vi, lane4);
    rygate<0x04, 0x04,  5>(vr, vi, lane4);
    rygate<0x02, 0x02,  6>(vr, vi, lane4);
    rygate<0x01, 0x01,  7>(vr, vi, lane4);
    applyD(vr, vi, lane4, 1);
    // ---- layer 2 ----
    rygate<0xC0, 0x80,  8>(vr, vi, lane4);
    rygate<0x60, 0xC0,  9>(vr, vi, lane4);
    rygate<0x30, 0xE0, 10>(vr, vi, lane4);
    rygate<0x18, 0xF0, 11>(vr, vi, lane4);
    rygate<0x0C, 0xF8, 12>(vr, vi, lane4);
    rygate<0x06, 0xFC, 13>(vr, vi, lane4);
    rygate<0x03, 0xFE, 14>(vr, vi, lane4);
    rygate<0x01, 0xFF, 15>(vr, vi, lane4);
    applyD(vr, vi, lane4, 2);
    // ---- layer 3 ----
    rygate<0xA0, 0x80, 16>(vr, vi, lane4);
    rygate<0x50, 0x40, 17>(vr, vi, lane4);
    rygate<0x28, 0xA0, 18>(vr, vi, lane4);
    rygate<0x14, 0x50, 19>(vr, vi, lane4);
    rygate<0x0A, 0xA8, 20>(vr, vi, lane4);
    rygate<0x05, 0x54, 21>(vr, vi, lane4);
    rygate<0x02, 0xAA, 22>(vr, vi, lane4);
    rygate<0x01, 0x55, 23>(vr, vi, lane4);
    applyD(vr, vi, lane4, 3);
    // ---- layer 4 (trailing diagonal dropped: |amp|^2 invariant) ----
    rygate<0xF0, 0x80, 24>(vr, vi, lane4);
    rygate<0x78, 0xC0, 25>(vr, vi, lane4);
    rygate<0x3C, 0x60, 26>(vr, vi, lane4);
    rygate<0x1E, 0x30, 27>(vr, vi, lane4);
    rygate<0x0F, 0x98, 28>(vr, vi, lane4);
    rygate<0x07, 0xCC, 29>(vr, vi, lane4);
    rygate<0x03, 0x66, 30>(vr, vi, lane4);
    rygate<0x01, 0x33, 31>(vr, vi, lane4);

    // ---- measurement: rows q0..q7 = 80,40,20,10,88,44,22,11 ----
    // Global C^2 folded into the sign multipliers (one scale for all z).
    float P0 = 0.f, S80 = 0.f, S40 = 0.f, S20 = 0.f, S10 = 0.f;
    float P1 = 0.f, S81 = 0.f, S41 = 0.f, S21 = 0.f, S11 = 0.f;
#pragma unroll
    for (int k = 0; k < 16; k++) {
        float r0 = lo32(vr[k]), i0 = lo32(vi[k]);
        float r1 = hi32(vr[k]), i1 = hi32(vi[k]);
        float p0 = r0 * r0 + i0 * i0;
        float p1 = r1 * r1 + i1 * i1;
        P0 += p0;                          P1 += p1;
        S80 += (k & 8) ? -p0 : p0;         S81 += (k & 8) ? -p1 : p1;
        S40 += (k & 4) ? -p0 : p0;         S41 += (k & 4) ? -p1 : p1;
        S20 += (k & 2) ? -p0 : p0;         S21 += (k & 2) ? -p1 : p1;
        S10 += (k & 1) ? -p0 : p0;         S11 += (k & 1) ? -p1 : p1;
    }
    float C2 = g_C2;
    float g8 = (lane4 & 8) ? -C2 : C2;
    float g4 = (lane4 & 4) ? -C2 : C2;
    float g2 = (lane4 & 2) ? -C2 : C2;
    float g1 = (lane4 & 1) ? -C2 : C2;
    float z[16];
    z[0]  = g8 * P0;   z[1]  = g4 * P0;   z[2]  = g2 * P0;   z[3]  = g1 * P0;
    z[4]  = g8 * S80;  z[5]  = g4 * S40;  z[6]  = g2 * S20;  z[7]  = g1 * S10;
    z[8]  = g8 * P1;   z[9]  = g4 * P1;   z[10] = g2 * P1;   z[11] = g1 * P1;
    z[12] = g8 * S81;  z[13] = g4 * S41;  z[14] = g2 * S21;  z[15] = g1 * S11;

#pragma unroll
    for (int off = 8; off >= 1; off >>= 1) {
#pragma unroll
        for (int i = 0; i < 16; i++)
            z[i] += __shfl_xor_sync(FULL, z[i], off);
    }
    if (lane4 == 0) {
        float4* o = (float4*)(out + warp * 32 + grp * 16);
        o[0] = make_float4(z[0],  z[1],  z[2],  z[3]);
        o[1] = make_float4(z[4],  z[5],  z[6],  z[7]);
        o[2] = make_float4(z[8],  z[9],  z[10], z[11]);
        o[3] = make_float4(z[12], z[13], z[14], z[15]);
    }
}

extern "C" void kernel_launch(void* const* d_in, const int* in_sizes, int n_in,
                              void* d_out, int out_size) {
    const float* x = (const float*)d_in[0];
    const float* w = (const float*)d_in[1];
    float* out = (float*)d_out;
    int B = in_sizes[0] / 8;
    int W = B / 4;   // 4 samples per warp (16-lane groups, f32x2-packed pairs)

    prep<<<1, 1024>>>(w);

    int threads = 128;
    long long total = (long long)W * 32;
    int blocks = (int)((total + threads - 1) / threads);
    qsim<<<blocks, threads>>>(x, out, W);
}

// round 12
// speedup vs baseline: 1.3897x; 1.1728x over previous
#include <cuda_runtime.h>
#include <cuda_bf16.h>

#define FULL 0xFFFFFFFFu
typedef unsigned long long ull;

// Per-gate tangent t = sin/cos for gates 8..31 (layers 2-4)
__device__ float g_t[32];
// Global scale C^2, C = prod of gate cosines for gates 8..31
__device__ float g_C2;
// Per-qubit fused Enc+D0+Layer1 op: A = ct*e^{-i lam/2}, B = st*e^{+i lam/2}
__device__ float4 g_W[8];
// Diagonal phase tables D1..D3 (j=1..3): 256 complex (cos, sin) each
__device__ float2 g_diag[4 * 256];

// Relabeled parity rows per gate (CNOTs folded; must match template R args)
__constant__ int c_rows[32] = {
    0x80,0x40,0x20,0x10,0x08,0x04,0x02,0x01,
    0x80,0xC0,0xE0,0xF0,0xF8,0xFC,0xFE,0xFF,
    0x80,0x40,0xA0,0x50,0xA8,0x54,0xAA,0x55,
    0x80,0xC0,0x60,0x30,0x98,0xCC,0x66,0x33
};

// ---- single fused prep kernel (1024 threads, one block) ----
__global__ void prep(const float* __restrict__ w) {
    __shared__ float s_lam[32], s_phi[32], s_ct[32], s_st[32];
    int t = threadIdx.x;
    if (t < 32) {
        int base = t * 3;
        float ta = w[base]     * 0.5f;
        float tb = w[base + 1] * 0.5f;
        float tc = w[base + 2] * 0.5f;
        float sa = sinf(ta), ca = cosf(ta);
        float sb = sinf(tb), cb = cosf(tb);
        float sc = sinf(tc), cc = cosf(tc);
        float m00r = cb * ca, m00i = sb * sa;
        float m01r = -sb * ca, m01i = -cb * sa;
        float x = cc * m00r + sc * m00i;
        float y = cc * m00i - sc * m00r;
        float z = cc * m01r + sc * m01i;
        float q = cc * m01i - sc * m01r;
        float ct = sqrtf(x * x + y * y);
        float st = sqrtf(z * z + q * q);
        float a = -atan2f(y, x);
        float b = atan2f(q, -z);
        g_t[t] = st / fmaxf(ct, 1e-30f);
        s_ct[t] = ct;  s_st[t] = st;
        s_lam[t] = a - b;
        s_phi[t] = a + b;
    }
    __syncthreads();
    if (t < 8) {
        // W_q: fused Enc+D0+Layer1 per qubit (exact, no tangent)
        float sn, cn;
        __sincosf(0.5f * s_lam[t], &sn, &cn);
        g_W[t] = make_float4(s_ct[t] * cn, -s_ct[t] * sn,   // A = ct e^{-i lam/2}
                             s_st[t] * cn,  s_st[t] * sn);  // B = st e^{+i lam/2}
    }
    if (t == 8) {
        float C = 1.f;
#pragma unroll
        for (int g = 8; g < 32; g++) C *= s_ct[g];
        g_C2 = C * C;
    }

    int j = t >> 8;
    int s = t & 255;
    if (j > 0) {
        float th = 0.f;
#pragma unroll
        for (int g = 0; g < 8; g++) {
            int gg = 8 * j + g;
            float sg = (__popc(c_rows[gg] & s) & 1) ? 1.f : -1.f;
            th += 0.5f * s_lam[gg] * sg;
        }
#pragma unroll
        for (int g = 0; g < 8; g++) {
            int gg = 8 * (j - 1) + g;
            float sg = (__popc(c_rows[gg] & s) & 1) ? 1.f : -1.f;
            th += 0.5f * s_phi[gg] * sg;
        }
        float sn, cn;
        __sincosf(th, &sn, &cn);
        g_diag[j * 256 + s] = make_float2(cn, sn);
    }
}

// ---- packed fp32x2 helpers: lanes = (sampleA, sampleB) ----
__device__ __forceinline__ ull fma2(ull a, ull b, ull c) {
    ull d; asm("fma.rn.f32x2 %0, %1, %2, %3;" : "=l"(d) : "l"(a), "l"(b), "l"(c));
    return d;
}
__device__ __forceinline__ ull mul2(ull a, ull b) {
    ull d; asm("mul.rn.f32x2 %0, %1, %2;" : "=l"(d) : "l"(a), "l"(b));
    return d;
}
__device__ __forceinline__ ull pack2(float lo, float hi) {
    ull d; asm("mov.b64 %0, {%1, %2};" : "=l"(d) : "f"(lo), "f"(hi));
    return d;
}
__device__ __forceinline__ float lo32(ull v) { return __uint_as_float((unsigned)v); }
__device__ __forceinline__ float hi32(ull v) { return __uint_as_float((unsigned)(v >> 32)); }

// packed complex multiply: (nr,ni) = (ar,ai)*(br,bi); bin = -bi packed
#define CMUL(nr, ni, ar, ai, br, bi, bin) \
    nr = fma2(ar, br, mul2(ai, bin));     \
    ni = fma2(ar, bi, mul2(ai, br));

// fetch qubit qq's full 2-vector for both samples of this group, packed
#define FETCHQ(qq, q0r, q0i, q0in, q1r, q1i, q1in) {                      \
    float a0r = __shfl_sync(FULL, v0r, gbase + (qq));                     \
    float a0i = __shfl_sync(FULL, v0i, gbase + (qq));                     \
    float a1r = __shfl_sync(FULL, v1r, gbase + (qq));                     \
    float a1i = __shfl_sync(FULL, v1i, gbase + (qq));                     \
    float b0r = __shfl_sync(FULL, v0r, gbase + 8 + (qq));                 \
    float b0i = __shfl_sync(FULL, v0i, gbase + 8 + (qq));                 \
    float b1r = __shfl_sync(FULL, v1r, gbase + 8 + (qq));                 \
    float b1i = __shfl_sync(FULL, v1i, gbase + 8 + (qq));                 \
    q0r = pack2(a0r, b0r); q0i = pack2(a0i, b0i); q0in = pack2(-a0i, -b0i); \
    q1r = pack2(a1r, b1r); q1i = pack2(a1i, b1i); q1in = pack2(-a1i, -b1i); }

// ---- fast-Givens Ry gate, 16-lane layout: lane4 = state bits 7..4, k = bits 3..0
// new[s] = a[s] + sigma(s)*t*a[s^M]; sigma = +1 if <R,s> odd. 0x6996 = 4-bit parity.
template<int M, int R, int G>
__device__ __forceinline__ void rygate(ull (&vr)[16], ull (&vi)[16], int lane4) {
    const float tg = g_t[G];
    constexpr int ML = (M >> 4) & 15;
    constexpr int MK = M & 15;
    constexpr int RL = (R >> 4) & 15;
    constexpr int RK = R & 15;
    constexpr int HB = (MK >= 8) ? 8 : (MK >= 4) ? 4 : (MK >= 2) ? 2 : 1;

    int pl = (0x6996 >> (lane4 & RL)) & 1;
    float tA = pl ? tg : -tg;
    ull tP = pack2(tA, tA);
    ull tN = pack2(-tA, -tA);

    if constexpr (ML != 0 && MK == 0) {
#pragma unroll
        for (int k = 0; k < 16; k++) {
            ull br = __shfl_xor_sync(FULL, vr[k], ML);
            ull bi = __shfl_xor_sync(FULL, vi[k], ML);
            ull sk = ((0x6996 >> (RK & k)) & 1) ? tN : tP;
            vr[k] = fma2(sk, br, vr[k]);
            vi[k] = fma2(sk, bi, vi[k]);
        }
    } else if constexpr (ML != 0) {
        // mixed: pair-complete — all shuffles of pair (k, k^MK) before any write
#pragma unroll
        for (int k = 0; k < 16; k++) {
            if ((k & HB) == 0) {
                const int k2 = k ^ MK;
                ull pr = __shfl_xor_sync(FULL, vr[k2], ML);
                ull pi = __shfl_xor_sync(FULL, vi[k2], ML);
                ull qr = __shfl_xor_sync(FULL, vr[k],  ML);
                ull qi = __shfl_xor_sync(FULL, vi[k],  ML);
                ull s1 = ((0x6996 >> (RK & k )) & 1) ? tN : tP;
                ull s2 = ((0x6996 >> (RK & k2)) & 1) ? tN : tP;
                vr[k]  = fma2(s1, pr, vr[k]);
                vi[k]  = fma2(s1, pi, vi[k]);
                vr[k2] = fma2(s2, qr, vr[k2]);
                vi[k2] = fma2(s2, qi, vi[k2]);
            }
        }
    } else {
#pragma unroll
        for (int k = 0; k < 16; k++) {
            if ((k & HB) == 0) {
                const int k2 = k ^ MK;
                ull s1 = ((0x6996 >> (RK & k )) & 1) ? tN : tP;
                ull s2 = ((0x6996 >> (RK & k2)) & 1) ? tN : tP;
                ull tr = vr[k], ti = vi[k], ur = vr[k2], ui = vi[k2];
                vr[k]  = fma2(s1, ur, tr);
                vi[k]  = fma2(s1, ui, ti);
                vr[k2] = fma2(s2, tr, ur);
                vi[k2] = fma2(s2, ti, ui);
            }
        }
    }
}

__device__ __forceinline__ void applyD(ull (&vr)[16], ull (&vi)[16], int lane4, int j) {
    const float4* __restrict__ t = (const float4*)(g_diag + j * 256 + lane4 * 16);
#pragma unroll
    for (int h = 0; h < 8; h++) {
        float4 p = __ldg(&t[h]);
        int k = 2 * h;
        {
            ull px = pack2(p.x, p.x), py = pack2(p.y, p.y), pyn = pack2(-p.y, -p.y);
            ull nr = fma2(px, vr[k], mul2(pyn, vi[k]));
            ull ni = fma2(px, vi[k], mul2(py,  vr[k]));
            vr[k] = nr; vi[k] = ni;
        }
        {
            ull px = pack2(p.z, p.z), py = pack2(p.w, p.w), pyn = pack2(-p.w, -p.w);
            ull nr = fma2(px, vr[k+1], mul2(pyn, vi[k+1]));
            ull ni = fma2(px, vi[k+1], mul2(py,  vr[k+1]));
            vr[k+1] = nr; vi[k+1] = ni;
        }
    }
}

__global__ void __launch_bounds__(128)
qsim(const float* __restrict__ x, float* __restrict__ out, int W) {
    int warp = (blockIdx.x * blockDim.x + threadIdx.x) >> 5;  // 0..W-1
    int lane = threadIdx.x & 31;
    if (warp >= W) return;
    int lane4 = lane & 15;    // state bits 7..4 (qubits 0..3)
    int grp = lane >> 4;      // half-warp group: samples (4w+2g, 4w+2g+1)
    int gbase = lane & 16;

    // ---- per-lane 1-qubit vector: v = W_q * (cos x/2, sin x/2)  (Enc+D0+L1) ----
    float xq = x[warp * 32 + lane];
    float sh, ch;
    __sincosf(0.5f * xq, &sh, &ch);
    float4 Wq = g_W[lane & 7];
    float v0r =  ch * Wq.x - sh * Wq.z;
    float v0i =  ch * Wq.y - sh * Wq.w;
    float v1r =  ch * Wq.z + sh * Wq.x;
    float v1i = -(ch * Wq.w + sh * Wq.y);

    // ---- lane-part product L over qubits 0..3 (lane4 bit (3-q)) ----
    ull Lr, Li;
#pragma unroll
    for (int qq = 0; qq < 4; qq++) {
        float a0r = __shfl_sync(FULL, v0r, gbase + qq);
        float a0i = __shfl_sync(FULL, v0i, gbase + qq);
        float a1r = __shfl_sync(FULL, v1r, gbase + qq);
        float a1i = __shfl_sync(FULL, v1i, gbase + qq);
        float b0r = __shfl_sync(FULL, v0r, gbase + 8 + qq);
        float b0i = __shfl_sync(FULL, v0i, gbase + 8 + qq);
        float b1r = __shfl_sync(FULL, v1r, gbase + 8 + qq);
        float b1i = __shfl_sync(FULL, v1i, gbase + 8 + qq);
        bool bit = (lane4 >> (3 - qq)) & 1;
        float srA = bit ? a1r : a0r;
        float siA = bit ? a1i : a0i;
        float srB = bit ? b1r : b0r;
        float siB = bit ? b1i : b0i;
        ull xr = pack2(srA, srB), xi = pack2(siA, siB), xin = pack2(-siA, -siB);
        if (qq == 0) { Lr = xr; Li = xi; }
        else {
            ull nLr, nLi;
            CMUL(nLr, nLi, Lr, Li, xr, xi, xin);
            Lr = nLr; Li = nLi;
        }
    }

    // ---- product tree over qubits 4..7 (k bits 3..0), L folded in ----
    ull vr[16], vi[16];
    {
        ull Er[2], Ei[2];
        {
            ull q0r, q0i, q0in, q1r, q1i, q1in;
            FETCHQ(4, q0r, q0i, q0in, q1r, q1i, q1in);
            CMUL(Er[0], Ei[0], Lr, Li, q0r, q0i, q0in);
            CMUL(Er[1], Ei[1], Lr, Li, q1r, q1i, q1in);
        }
        ull Fr[4], Fi[4];
        {
            ull q0r, q0i, q0in, q1r, q1i, q1in;
            FETCHQ(5, q0r, q0i, q0in, q1r, q1i, q1in);
#pragma unroll
            for (int b = 0; b < 2; b++) {
                CMUL(Fr[2*b],   Fi[2*b],   Er[b], Ei[b], q0r, q0i, q0in);
                CMUL(Fr[2*b+1], Fi[2*b+1], Er[b], Ei[b], q1r, q1i, q1in);
            }
        }
        ull Gr[8], Gi[8];
        {
            ull q0r, q0i, q0in, q1r, q1i, q1in;
            FETCHQ(6, q0r, q0i, q0in, q1r, q1i, q1in);
#pragma unroll
            for (int b = 0; b < 4; b++) {
                CMUL(Gr[2*b],   Gi[2*b],   Fr[b], Fi[b], q0r, q0i, q0in);
                CMUL(Gr[2*b+1], Gi[2*b+1], Fr[b], Fi[b], q1r, q1i, q1in);
            }
        }
        {
            ull q0r, q0i, q0in, q1r, q1i, q1in;
            FETCHQ(7, q0r, q0i, q0in, q1r, q1i, q1in);
#pragma unroll
            for (int b = 0; b < 8; b++) {
                CMUL(vr[2*b],   vi[2*b],   Gr[b], Gi[b], q0r, q0i, q0in);
                CMUL(vr[2*b+1], vi[2*b+1], Gr[b], Gi[b], q1r, q1i, q1in);
            }
        }
    }

    applyD(vr, vi, lane4, 1);
    // ---- layer 2 ----
    rygate<0xC0, 0x80,  8>(vr, vi, lane4);
    rygate<0x60, 0xC0,  9>(vr, vi, lane4);
    rygate<0x30, 0xE0, 10>(vr, vi, lane4);
    rygate<0x18, 0xF0, 11>(vr, vi, lane4);
    rygate<0x0C, 0xF8, 12>(vr, vi, lane4);
    rygate<0x06, 0xFC, 13>(vr, vi, lane4);
    rygate<0x03, 0xFE, 14>(vr, vi, lane4);
    rygate<0x01, 0xFF, 15>(vr, vi, lane4);
    applyD(vr, vi, lane4, 2);
    // ---- layer 3 ----
    rygate<0xA0, 0x80, 16>(vr, vi, lane4);
    rygate<0x50, 0x40, 17>(vr, vi, lane4);
    rygate<0x28, 0xA0, 18>(vr, vi, lane4);
    rygate<0x14, 0x50, 19>(vr, vi, lane4);
    rygate<0x0A, 0xA8, 20>(vr, vi, lane4);
    rygate<0x05, 0x54, 21>(vr, vi, lane4);
    rygate<0x02, 0xAA, 22>(vr, vi, lane4);
    rygate<0x01, 0x55, 23>(vr, vi, lane4);
    applyD(vr, vi, lane4, 3);
    // ---- layer 4 (trailing diagonal dropped: |amp|^2 invariant) ----
    rygate<0xF0, 0x80, 24>(vr, vi, lane4);
    rygate<0x78, 0xC0, 25>(vr, vi, lane4);
    rygate<0x3C, 0x60, 26>(vr, vi, lane4);
    rygate<0x1E, 0x30, 27>(vr, vi, lane4);
    rygate<0x0F, 0x98, 28>(vr, vi, lane4);
    rygate<0x07, 0xCC, 29>(vr, vi, lane4);
    rygate<0x03, 0x66, 30>(vr, vi, lane4);
    rygate<0x01, 0x33, 31>(vr, vi, lane4);

    // ---- measurement: rows q0..q7 = 80,40,20,10,88,44,22,11; C^2 folded in ----
    float P0 = 0.f, S80 = 0.f, S40 = 0.f, S20 = 0.f, S10 = 0.f;
    float P1 = 0.f, S81 = 0.f, S41 = 0.f, S21 = 0.f, S11 = 0.f;
#pragma unroll
    for (int k = 0; k < 16; k++) {
        float r0 = lo32(vr[k]), i0 = lo32(vi[k]);
        float r1 = hi32(vr[k]), i1 = hi32(vi[k]);
        float p0 = r0 * r0 + i0 * i0;
        float p1 = r1 * r1 + i1 * i1;
        P0 += p0;                          P1 += p1;
        S80 += (k & 8) ? -p0 : p0;         S81 += (k & 8) ? -p1 : p1;
        S40 += (k & 4) ? -p0 : p0;         S41 += (k & 4) ? -p1 : p1;
        S20 += (k & 2) ? -p0 : p0;         S21 += (k & 2) ? -p1 : p1;
        S10 += (k & 1) ? -p0 : p0;         S11 += (k & 1) ? -p1 : p1;
    }
    float C2 = g_C2;
    float g8 = (lane4 & 8) ? -C2 : C2;
    float g4 = (lane4 & 4) ? -C2 : C2;
    float g2 = (lane4 & 2) ? -C2 : C2;
    float g1 = (lane4 & 1) ? -C2 : C2;
    float z[16];
    z[0]  = g8 * P0;   z[1]  = g4 * P0;   z[2]  = g2 * P0;   z[3]  = g1 * P0;
    z[4]  = g8 * S80;  z[5]  = g4 * S40;  z[6]  = g2 * S20;  z[7]  = g1 * S10;
    z[8]  = g8 * P1;   z[9]  = g4 * P1;   z[10] = g2 * P1;   z[11] = g1 * P1;
    z[12] = g8 * S81;  z[13] = g4 * S41;  z[14] = g2 * S21;  z[15] = g1 * S11;

#pragma unroll
    for (int off = 8; off >= 1; off >>= 1) {
#pragma unroll
        for (int i = 0; i < 16; i++)
            z[i] += __shfl_xor_sync(FULL, z[i], off);
    }
    if (lane4 == 0) {
        float4* o = (float4*)(out + warp * 32 + grp * 16);
        o[0] = make_float4(z[0],  z[1],  z[2],  z[3]);
        o[1] = make_float4(z[4],  z[5],  z[6],  z[7]);
        o[2] = make_float4(z[8],  z[9],  z[10], z[11]);
        o[3] = make_float4(z[12], z[13], z[14], z[15]);
    }
}

extern "C" void kernel_launch(void* const* d_in, const int* in_sizes, int n_in,
                              void* d_out, int out_size) {
    const float* x = (const float*)d_in[0];
    const float* w = (const float*)d_in[1];
    float* out = (float*)d_out;
    int B = in_sizes[0] / 8;
    int W = B / 4;   // 4 samples per warp (16-lane groups, f32x2-packed pairs)

    prep<<<1, 1024>>>(w);

    int threads = 128;
    long long total = (long long)W * 32;
    int blocks = (int)((total + threads - 1) / threads);
    qsim<<<blocks, threads>>>(x, out, W);
}

// round 13
// speedup vs baseline: 1.8058x; 1.2994x over previous
#include <cuda_runtime.h>
#include <cuda_bf16.h>

#define FULL 0xFFFFFFFFu
typedef unsigned long long ull;

// Relabeled parity rows per gate (CNOTs folded; must match template R args)
__constant__ int c_rows[32] = {
    0x80,0x40,0x20,0x10,0x08,0x04,0x02,0x01,
    0x80,0xC0,0xE0,0xF0,0xF8,0xFC,0xFE,0xFF,
    0x80,0x40,0xA0,0x50,0xA8,0x54,0xAA,0x55,
    0x80,0xC0,0x60,0x30,0x98,0xCC,0x66,0x33
};

// ---- packed fp32x2 helpers: lanes = (sampleA, sampleB) ----
__device__ __forceinline__ ull fma2(ull a, ull b, ull c) {
    ull d; asm("fma.rn.f32x2 %0, %1, %2, %3;" : "=l"(d) : "l"(a), "l"(b), "l"(c));
    return d;
}
__device__ __forceinline__ ull mul2(ull a, ull b) {
    ull d; asm("mul.rn.f32x2 %0, %1, %2;" : "=l"(d) : "l"(a), "l"(b));
    return d;
}
__device__ __forceinline__ ull pack2(float lo, float hi) {
    ull d; asm("mov.b64 %0, {%1, %2};" : "=l"(d) : "f"(lo), "f"(hi));
    return d;
}
__device__ __forceinline__ float lo32(ull v) { return __uint_as_float((unsigned)v); }
__device__ __forceinline__ float hi32(ull v) { return __uint_as_float((unsigned)(v >> 32)); }

// packed complex multiply: (nr,ni) = (ar,ai)*(br,bi); bin = -bi packed
#define CMUL(nr, ni, ar, ai, br, bi, bin) \
    nr = fma2(ar, br, mul2(ai, bin));     \
    ni = fma2(ar, bi, mul2(ai, br));

// fetch qubit qq's full 2-vector for both samples of this group, packed
#define FETCHQ(qq, q0r, q0i, q0in, q1r, q1i, q1in) {                      \
    float a0r = __shfl_sync(FULL, v0r, gbase + (qq));                     \
    float a0i = __shfl_sync(FULL, v0i, gbase + (qq));                     \
    float a1r = __shfl_sync(FULL, v1r, gbase + (qq));                     \
    float a1i = __shfl_sync(FULL, v1i, gbase + (qq));                     \
    float b0r = __shfl_sync(FULL, v0r, gbase + 8 + (qq));                 \
    float b0i = __shfl_sync(FULL, v0i, gbase + 8 + (qq));                 \
    float b1r = __shfl_sync(FULL, v1r, gbase + 8 + (qq));                 \
    float b1i = __shfl_sync(FULL, v1i, gbase + 8 + (qq));                 \
    q0r = pack2(a0r, b0r); q0i = pack2(a0i, b0i); q0in = pack2(-a0i, -b0i); \
    q1r = pack2(a1r, b1r); q1i = pack2(a1i, b1i); q1in = pack2(-a1i, -b1i); }

// ---- fast-Givens Ry gate, 16-lane layout: lane4 = state bits 7..4, k = bits 3..0
// new[s] = a[s] + sigma(s)*t*a[s^M]; sigma = +1 if <R,s> odd. 0x6996 = 4-bit parity.
template<int M, int R, int G>
__device__ __forceinline__ void rygate(ull (&vr)[16], ull (&vi)[16], int lane4,
                                       const float* __restrict__ s_t) {
    const float tg = s_t[G];
    constexpr int ML = (M >> 4) & 15;
    constexpr int MK = M & 15;
    constexpr int RL = (R >> 4) & 15;
    constexpr int RK = R & 15;
    constexpr int HB = (MK >= 8) ? 8 : (MK >= 4) ? 4 : (MK >= 2) ? 2 : 1;

    int pl = (0x6996 >> (lane4 & RL)) & 1;
    float tA = pl ? tg : -tg;
    ull tP = pack2(tA, tA);
    ull tN = pack2(-tA, -tA);

    if constexpr (ML != 0 && MK == 0) {
#pragma unroll
        for (int k = 0; k < 16; k++) {
            ull br = __shfl_xor_sync(FULL, vr[k], ML);
            ull bi = __shfl_xor_sync(FULL, vi[k], ML);
            ull sk = ((0x6996 >> (RK & k)) & 1) ? tN : tP;
            vr[k] = fma2(sk, br, vr[k]);
            vi[k] = fma2(sk, bi, vi[k]);
        }
    } else if constexpr (ML != 0) {
        // mixed: pair-complete — all shuffles of pair (k, k^MK) before any write
#pragma unroll
        for (int k = 0; k < 16; k++) {
            if ((k & HB) == 0) {
                const int k2 = k ^ MK;
                ull pr = __shfl_xor_sync(FULL, vr[k2], ML);
                ull pi = __shfl_xor_sync(FULL, vi[k2], ML);
                ull qr = __shfl_xor_sync(FULL, vr[k],  ML);
                ull qi = __shfl_xor_sync(FULL, vi[k],  ML);
                ull s1 = ((0x6996 >> (RK & k )) & 1) ? tN : tP;
                ull s2 = ((0x6996 >> (RK & k2)) & 1) ? tN : tP;
                vr[k]  = fma2(s1, pr, vr[k]);
                vi[k]  = fma2(s1, pi, vi[k]);
                vr[k2] = fma2(s2, qr, vr[k2]);
                vi[k2] = fma2(s2, qi, vi[k2]);
            }
        }
    } else {
#pragma unroll
        for (int k = 0; k < 16; k++) {
            if ((k & HB) == 0) {
                const int k2 = k ^ MK;
                ull s1 = ((0x6996 >> (RK & k )) & 1) ? tN : tP;
                ull s2 = ((0x6996 >> (RK & k2)) & 1) ? tN : tP;
                ull tr = vr[k], ti = vi[k], ur = vr[k2], ui = vi[k2];
                vr[k]  = fma2(s1, ur, tr);
                vi[k]  = fma2(s1, ui, ti);
                vr[k2] = fma2(s2, tr, ur);
                vi[k2] = fma2(s2, ti, ui);
            }
        }
    }
}

// diag table transposed in smem: tbl[h*16 + lane4] = phases of slots
// (lane4*16 + 2h, lane4*16 + 2h + 1)  -> conflict-free 16-lane float4 reads
__device__ __forceinline__ void applyD(ull (&vr)[16], ull (&vi)[16], int lane4,
                                       const float4* __restrict__ tbl) {
#pragma unroll
    for (int h = 0; h < 8; h++) {
        float4 p = tbl[h * 16 + lane4];
        int k = 2 * h;
        {
            ull px = pack2(p.x, p.x), py = pack2(p.y, p.y), pyn = pack2(-p.y, -p.y);
            ull nr = fma2(px, vr[k], mul2(pyn, vi[k]));
            ull ni = fma2(px, vi[k], mul2(py,  vr[k]));
            vr[k] = nr; vi[k] = ni;
        }
        {
            ull px = pack2(p.z, p.z), py = pack2(p.w, p.w), pyn = pack2(-p.w, -p.w);
            ull nr = fma2(px, vr[k+1], mul2(pyn, vi[k+1]));
            ull ni = fma2(px, vi[k+1], mul2(py,  vr[k+1]));
            vr[k+1] = nr; vi[k+1] = ni;
        }
    }
}

__global__ void __launch_bounds__(128)
qsim(const float* __restrict__ x, const float* __restrict__ w,
     float* __restrict__ out, int W) {
    // ---- per-block inlined prep (identical in every block, deterministic) ----
    __shared__ float4 s_diag4[3 * 128];   // tables j=1..3, transposed
    __shared__ float  s_t[32];
    __shared__ float4 s_W[8];
    __shared__ float  s_C2;
    __shared__ float  s_lam[32], s_phi[32], s_ct[32], s_st[32];

    int tid = threadIdx.x;
    if (tid < 32) {
        int base = tid * 3;
        float sa, ca, sb, cb, sc, cc;
        __sincosf(w[base]     * 0.5f, &sa, &ca);
        __sincosf(w[base + 1] * 0.5f, &sb, &cb);
        __sincosf(w[base + 2] * 0.5f, &sc, &cc);
        float m00r = cb * ca, m00i = sb * sa;
        float m01r = -sb * ca, m01i = -cb * sa;
        float X = cc * m00r + sc * m00i;
        float Y = cc * m00i - sc * m00r;
        float Z = cc * m01r + sc * m01i;
        float Q = cc * m01i - sc * m01r;
        float ct = sqrtf(X * X + Y * Y);
        float st = sqrtf(Z * Z + Q * Q);
        float a = -atan2f(Y, X);
        float b = atan2f(Q, -Z);
        s_t[tid]  = st / fmaxf(ct, 1e-30f);
        s_ct[tid] = ct;  s_st[tid] = st;
        s_lam[tid] = a - b;
        s_phi[tid] = a + b;
    }
    __syncthreads();
    if (tid < 8) {
        float sn, cn;
        __sincosf(0.5f * s_lam[tid], &sn, &cn);
        s_W[tid] = make_float4(s_ct[tid] * cn, -s_ct[tid] * sn,   // A = ct e^{-i lam/2}
                               s_st[tid] * cn,  s_st[tid] * sn);  // B = st e^{+i lam/2}
    }
    if (tid == 8) {
        float C = 1.f;
#pragma unroll
        for (int g = 8; g < 32; g++) C *= s_ct[g];
        s_C2 = C * C;
    }
    // diag tables: 768 entries, 6 per thread
    {
        float2* s_diag2 = (float2*)s_diag4;
#pragma unroll
        for (int e = 0; e < 6; e++) {
            int n = tid * 6 + e;      // 0..767
            int j = n >> 8;           // table index 0..2 (= D_{j+1})
            int s = n & 255;
            float th = 0.f;
#pragma unroll
            for (int g = 0; g < 8; g++) {
                int g1 = 8 * (j + 1) + g;   // lam of layer j+2's gates... (lam of D_{j+1})
                float sg1 = (__popc(c_rows[g1] & s) & 1) ? 1.f : -1.f;
                th += 0.5f * s_lam[g1] * sg1;
                int g0 = 8 * j + g;
                float sg0 = (__popc(c_rows[g0] & s) & 1) ? 1.f : -1.f;
                th += 0.5f * s_phi[g0] * sg0;
            }
            float sn, cn;
            __sincosf(th, &sn, &cn);
            int kk = s & 15, l4 = s >> 4;
            s_diag2[j * 256 + ((kk >> 1) * 16 + l4) * 2 + (kk & 1)] = make_float2(cn, sn);
        }
    }
    __syncthreads();

    // ---- main body ----
    int warp = (blockIdx.x * blockDim.x + threadIdx.x) >> 5;
    int lane = threadIdx.x & 31;
    if (warp >= W) return;          // grid is exact for B=16384; guard is vestigial
    int lane4 = lane & 15;
    int grp = lane >> 4;
    int gbase = lane & 16;

    // per-lane 1-qubit vector: v = W_q * (cos x/2, sin x/2)  (Enc+D0+L1)
    float xq = x[warp * 32 + lane];
    float sh, ch;
    __sincosf(0.5f * xq, &sh, &ch);
    float4 Wq = s_W[lane & 7];
    float v0r =  ch * Wq.x - sh * Wq.z;
    float v0i =  ch * Wq.y - sh * Wq.w;
    float v1r =  ch * Wq.z + sh * Wq.x;
    float v1i = -(ch * Wq.w + sh * Wq.y);

    // lane-part product L over qubits 0..3 (lane4 bit (3-q))
    ull Lr, Li;
#pragma unroll
    for (int qq = 0; qq < 4; qq++) {
        float a0r = __shfl_sync(FULL, v0r, gbase + qq);
        float a0i = __shfl_sync(FULL, v0i, gbase + qq);
        float a1r = __shfl_sync(FULL, v1r, gbase + qq);
        float a1i = __shfl_sync(FULL, v1i, gbase + qq);
        float b0r = __shfl_sync(FULL, v0r, gbase + 8 + qq);
        float b0i = __shfl_sync(FULL, v0i, gbase + 8 + qq);
        float b1r = __shfl_sync(FULL, v1r, gbase + 8 + qq);
        float b1i = __shfl_sync(FULL, v1i, gbase + 8 + qq);
        bool bit = (lane4 >> (3 - qq)) & 1;
        float srA = bit ? a1r : a0r;
        float siA = bit ? a1i : a0i;
        float srB = bit ? b1r : b0r;
        float siB = bit ? b1i : b0i;
        ull xr = pack2(srA, srB), xi = pack2(siA, siB), xin = pack2(-siA, -siB);
        if (qq == 0) { Lr = xr; Li = xi; }
        else {
            ull nLr, nLi;
            CMUL(nLr, nLi, Lr, Li, xr, xi, xin);
            Lr = nLr; Li = nLi;
        }
    }

    // product tree over qubits 4..7 (k bits 3..0), L folded in
    ull vr[16], vi[16];
    {
        ull Er[2], Ei[2];
        {
            ull q0r, q0i, q0in, q1r, q1i, q1in;
            FETCHQ(4, q0r, q0i, q0in, q1r, q1i, q1in);
            CMUL(Er[0], Ei[0], Lr, Li, q0r, q0i, q0in);
            CMUL(Er[1], Ei[1], Lr, Li, q1r, q1i, q1in);
        }
        ull Fr[4], Fi[4];
        {
            ull q0r, q0i, q0in, q1r, q1i, q1in;
            FETCHQ(5, q0r, q0i, q0in, q1r, q1i, q1in);
#pragma unroll
            for (int b = 0; b < 2; b++) {
                CMUL(Fr[2*b],   Fi[2*b],   Er[b], Ei[b], q0r, q0i, q0in);
                CMUL(Fr[2*b+1], Fi[2*b+1], Er[b], Ei[b], q1r, q1i, q1in);
            }
        }
        ull Gr[8], Gi[8];
        {
            ull q0r, q0i, q0in, q1r, q1i, q1in;
            FETCHQ(6, q0r, q0i, q0in, q1r, q1i, q1in);
#pragma unroll
            for (int b = 0; b < 4; b++) {
                CMUL(Gr[2*b],   Gi[2*b],   Fr[b], Fi[b], q0r, q0i, q0in);
                CMUL(Gr[2*b+1], Gi[2*b+1], Fr[b], Fi[b], q1r, q1i, q1in);
            }
        }
        {
            ull q0r, q0i, q0in, q1r, q1i, q1in;
            FETCHQ(7, q0r, q0i, q0in, q1r, q1i, q1in);
#pragma unroll
            for (int b = 0; b < 8; b++) {
                CMUL(vr[2*b],   vi[2*b],   Gr[b], Gi[b], q0r, q0i, q0in);
                CMUL(vr[2*b+1], vi[2*b+1], Gr[b], Gi[b], q1r, q1i, q1in);
            }
        }
    }

    applyD(vr, vi, lane4, s_diag4);
    // ---- layer 2 ----
    rygate<0xC0, 0x80,  8>(vr, vi, lane4, s_t);
    rygate<0x60, 0xC0,  9>(vr, vi, lane4, s_t);
    rygate<0x30, 0xE0, 10>(vr, vi, lane4, s_t);
    rygate<0x18, 0xF0, 11>(vr, vi, lane4, s_t);
    rygate<0x0C, 0xF8, 12>(vr, vi, lane4, s_t);
    rygate<0x06, 0xFC, 13>(vr, vi, lane4, s_t);
    rygate<0x03, 0xFE, 14>(vr, vi, lane4, s_t);
    rygate<0x01, 0xFF, 15>(vr, vi, lane4, s_t);
    applyD(vr, vi, lane4, s_diag4 + 128);
    // ---- layer 3 ----
    rygate<0xA0, 0x80, 16>(vr, vi, lane4, s_t);
    rygate<0x50, 0x40, 17>(vr, vi, lane4, s_t);
    rygate<0x28, 0xA0, 18>(vr, vi, lane4, s_t);
    rygate<0x14, 0x50, 19>(vr, vi, lane4, s_t);
    rygate<0x0A, 0xA8, 20>(vr, vi, lane4, s_t);
    rygate<0x05, 0x54, 21>(vr, vi, lane4, s_t);
    rygate<0x02, 0xAA, 22>(vr, vi, lane4, s_t);
    rygate<0x01, 0x55, 23>(vr, vi, lane4, s_t);
    applyD(vr, vi, lane4, s_diag4 + 256);
    // ---- layer 4 (trailing diagonal dropped: |amp|^2 invariant) ----
    rygate<0xF0, 0x80, 24>(vr, vi, lane4, s_t);
    rygate<0x78, 0xC0, 25>(vr, vi, lane4, s_t);
    rygate<0x3C, 0x60, 26>(vr, vi, lane4, s_t);
    rygate<0x1E, 0x30, 27>(vr, vi, lane4, s_t);
    rygate<0x0F, 0x98, 28>(vr, vi, lane4, s_t);
    rygate<0x07, 0xCC, 29>(vr, vi, lane4, s_t);
    rygate<0x03, 0x66, 30>(vr, vi, lane4, s_t);
    rygate<0x01, 0x33, 31>(vr, vi, lane4, s_t);

    // ---- measurement: rows q0..q7 = 80,40,20,10,88,44,22,11; C^2 folded in ----
    float P0 = 0.f, S80 = 0.f, S40 = 0.f, S20 = 0.f, S10 = 0.f;
    float P1 = 0.f, S81 = 0.f, S41 = 0.f, S21 = 0.f, S11 = 0.f;
#pragma unroll
    for (int k = 0; k < 16; k++) {
        float r0 = lo32(vr[k]), i0 = lo32(vi[k]);
        float r1 = hi32(vr[k]), i1 = hi32(vi[k]);
        float p0 = r0 * r0 + i0 * i0;
        float p1 = r1 * r1 + i1 * i1;
        P0 += p0;                          P1 += p1;
        S80 += (k & 8) ? -p0 : p0;         S81 += (k & 8) ? -p1 : p1;
        S40 += (k & 4) ? -p0 : p0;         S41 += (k & 4) ? -p1 : p1;
        S20 += (k & 2) ? -p0 : p0;         S21 += (k & 2) ? -p1 : p1;
        S10 += (k & 1) ? -p0 : p0;         S11 += (k & 1) ? -p1 : p1;
    }
    float C2 = s_C2;
    float g8 = (lane4 & 8) ? -C2 : C2;
    float g4 = (lane4 & 4) ? -C2 : C2;
    float g2 = (lane4 & 2) ? -C2 : C2;
    float g1 = (lane4 & 1) ? -C2 : C2;
    float z[16];
    z[0]  = g8 * P0;   z[1]  = g4 * P0;   z[2]  = g2 * P0;   z[3]  = g1 * P0;
    z[4]  = g8 * S80;  z[5]  = g4 * S40;  z[6]  = g2 * S20;  z[7]  = g1 * S10;
    z[8]  = g8 * P1;   z[9]  = g4 * P1;   z[10] = g2 * P1;   z[11] = g1 * P1;
    z[12] = g8 * S81;  z[13] = g4 * S41;  z[14] = g2 * S21;  z[15] = g1 * S11;

#pragma unroll
    for (int off = 8; off >= 1; off >>= 1) {
#pragma unroll
        for (int i = 0; i < 16; i++)
            z[i] += __shfl_xor_sync(FULL, z[i], off);
    }
    if (lane4 == 0) {
        float4* o = (float4*)(out + warp * 32 + grp * 16);
        o[0] = make_float4(z[0],  z[1],  z[2],  z[3]);
        o[1] = make_float4(z[4],  z[5],  z[6],  z[7]);
        o[2] = make_float4(z[8],  z[9],  z[10], z[11]);
        o[3] = make_float4(z[12], z[13], z[14], z[15]);
    }
}

extern "C" void kernel_launch(void* const* d_in, const int* in_sizes, int n_in,
                              void* d_out, int out_size) {
    const float* x = (const float*)d_in[0];
    const float* w = (const float*)d_in[1];
    float* out = (float*)d_out;
    int B = in_sizes[0] / 8;
    int W = B / 4;   // 4 samples per warp (16-lane groups, f32x2-packed pairs)

    int threads = 128;
    long long total = (long long)W * 32;
    int blocks = (int)((total + threads - 1) / threads);
    qsim<<<blocks, threads>>>(x, w, out, W);
}

// round 14
// speedup vs baseline: 1.9694x; 1.0906x over previous
#include <cuda_runtime.h>
#include <cuda_bf16.h>

#define FULL 0xFFFFFFFFu
typedef unsigned long long ull;

// Relabeled parity rows per gate (CNOTs folded; must match template R args)
__constant__ int c_rows[32] = {
    0x80,0x40,0x20,0x10,0x08,0x04,0x02,0x01,
    0x80,0xC0,0xE0,0xF0,0xF8,0xFC,0xFE,0xFF,
    0x80,0x40,0xA0,0x50,0xA8,0x54,0xAA,0x55,
    0x80,0xC0,0x60,0x30,0x98,0xCC,0x66,0x33
};

// ---- packed fp32x2 helpers: lanes = (sampleA, sampleB) ----
__device__ __forceinline__ ull fma2(ull a, ull b, ull c) {
    ull d; asm("fma.rn.f32x2 %0, %1, %2, %3;" : "=l"(d) : "l"(a), "l"(b), "l"(c));
    return d;
}
__device__ __forceinline__ ull mul2(ull a, ull b) {
    ull d; asm("mul.rn.f32x2 %0, %1, %2;" : "=l"(d) : "l"(a), "l"(b));
    return d;
}
__device__ __forceinline__ ull pack2(float lo, float hi) {
    ull d; asm("mov.b64 %0, {%1, %2};" : "=l"(d) : "f"(lo), "f"(hi));
    return d;
}
__device__ __forceinline__ float lo32(ull v) { return __uint_as_float((unsigned)v); }
__device__ __forceinline__ float hi32(ull v) { return __uint_as_float((unsigned)(v >> 32)); }

// packed complex multiply: (nr,ni) = (ar,ai)*(br,bi); bin = -bi packed
#define CMUL(nr, ni, ar, ai, br, bi, bin) \
    nr = fma2(ar, br, mul2(ai, bin));     \
    ni = fma2(ar, bi, mul2(ai, br));

// fetch qubit qq's full 2-vector for both samples of this group, packed
#define FETCHQ(qq, q0r, q0i, q0in, q1r, q1i, q1in) {                      \
    float a0r = __shfl_sync(FULL, v0r, gbase + (qq));                     \
    float a0i = __shfl_sync(FULL, v0i, gbase + (qq));                     \
    float a1r = __shfl_sync(FULL, v1r, gbase + (qq));                     \
    float a1i = __shfl_sync(FULL, v1i, gbase + (qq));                     \
    float b0r = __shfl_sync(FULL, v0r, gbase + 8 + (qq));                 \
    float b0i = __shfl_sync(FULL, v0i, gbase + 8 + (qq));                 \
    float b1r = __shfl_sync(FULL, v1r, gbase + 8 + (qq));                 \
    float b1i = __shfl_sync(FULL, v1i, gbase + 8 + (qq));                 \
    q0r = pack2(a0r, b0r); q0i = pack2(a0i, b0i); q0in = pack2(-a0i, -b0i); \
    q1r = pack2(a1r, b1r); q1i = pack2(a1i, b1i); q1in = pack2(-a1i, -b1i); }

// ---- fast-Givens Ry gate, 16-lane layout: lane4 = state bits 7..4, k = bits 3..0
// new[s] = a[s] + sigma(s)*t*a[s^M]; sigma = +1 if <R,s> odd. 0x6996 = 4-bit parity.
template<int M, int R, int G>
__device__ __forceinline__ void rygate(ull (&vr)[16], ull (&vi)[16], int lane4,
                                       const float* __restrict__ s_t) {
    const float tg = s_t[G];
    constexpr int ML = (M >> 4) & 15;
    constexpr int MK = M & 15;
    constexpr int RL = (R >> 4) & 15;
    constexpr int RK = R & 15;
    constexpr int HB = (MK >= 8) ? 8 : (MK >= 4) ? 4 : (MK >= 2) ? 2 : 1;

    int pl = (0x6996 >> (lane4 & RL)) & 1;
    float tA = pl ? tg : -tg;
    ull tP = pack2(tA, tA);
    ull tN = pack2(-tA, -tA);

    if constexpr (ML != 0 && MK == 0) {
#pragma unroll
        for (int k = 0; k < 16; k++) {
            ull br = __shfl_xor_sync(FULL, vr[k], ML);
            ull bi = __shfl_xor_sync(FULL, vi[k], ML);
            ull sk = ((0x6996 >> (RK & k)) & 1) ? tN : tP;
            vr[k] = fma2(sk, br, vr[k]);
            vi[k] = fma2(sk, bi, vi[k]);
        }
    } else if constexpr (ML != 0) {
        // mixed: pair-complete — all shuffles of pair (k, k^MK) before any write
#pragma unroll
        for (int k = 0; k < 16; k++) {
            if ((k & HB) == 0) {
                const int k2 = k ^ MK;
                ull pr = __shfl_xor_sync(FULL, vr[k2], ML);
                ull pi = __shfl_xor_sync(FULL, vi[k2], ML);
                ull qr = __shfl_xor_sync(FULL, vr[k],  ML);
                ull qi = __shfl_xor_sync(FULL, vi[k],  ML);
                ull s1 = ((0x6996 >> (RK & k )) & 1) ? tN : tP;
                ull s2 = ((0x6996 >> (RK & k2)) & 1) ? tN : tP;
                vr[k]  = fma2(s1, pr, vr[k]);
                vi[k]  = fma2(s1, pi, vi[k]);
                vr[k2] = fma2(s2, qr, vr[k2]);
                vi[k2] = fma2(s2, qi, vi[k2]);
            }
        }
    } else {
#pragma unroll
        for (int k = 0; k < 16; k++) {
            if ((k & HB) == 0) {
                const int k2 = k ^ MK;
                ull s1 = ((0x6996 >> (RK & k )) & 1) ? tN : tP;
                ull s2 = ((0x6996 >> (RK & k2)) & 1) ? tN : tP;
                ull tr = vr[k], ti = vi[k], ur = vr[k2], ui = vi[k2];
                vr[k]  = fma2(s1, ur, tr);
                vi[k]  = fma2(s1, ui, ti);
                vr[k2] = fma2(s2, tr, ur);
                vi[k2] = fma2(s2, ti, ui);
            }
        }
    }
}

// diag table transposed in smem: tbl[h*16 + lane4] = phases of slots
// (lane4*16 + 2h, lane4*16 + 2h + 1)  -> conflict-free 16-lane float4 reads
__device__ __forceinline__ void applyD(ull (&vr)[16], ull (&vi)[16], int lane4,
                                       const float4* __restrict__ tbl) {
#pragma unroll
    for (int h = 0; h < 8; h++) {
        float4 p = tbl[h * 16 + lane4];
        int k = 2 * h;
        {
            ull px = pack2(p.x, p.x), py = pack2(p.y, p.y), pyn = pack2(-p.y, -p.y);
            ull nr = fma2(px, vr[k], mul2(pyn, vi[k]));
            ull ni = fma2(px, vi[k], mul2(py,  vr[k]));
            vr[k] = nr; vi[k] = ni;
        }
        {
            ull px = pack2(p.z, p.z), py = pack2(p.w, p.w), pyn = pack2(-p.w, -p.w);
            ull nr = fma2(px, vr[k+1], mul2(pyn, vi[k+1]));
            ull ni = fma2(px, vi[k+1], mul2(py,  vr[k+1]));
            vr[k+1] = nr; vi[k+1] = ni;
        }
    }
}

__global__ void __launch_bounds__(128)
qsim(const float* __restrict__ x, const float* __restrict__ w,
     float* __restrict__ out, int W) {
    // ---- per-block inlined prep (identical in every block, deterministic) ----
    __shared__ float4 s_diag4[3 * 128];   // tables j=1..3, transposed
    __shared__ float  s_t[32];
    __shared__ float4 s_W[8];
    __shared__ float  s_C2;
    __shared__ float  s_lam[32], s_phi[32], s_ct[32], s_st[32];

    int tid = threadIdx.x;
    if (tid < 32) {
        int base = tid * 3;
        float sa, ca, sb, cb, sc, cc;
        __sincosf(w[base]     * 0.5f, &sa, &ca);
        __sincosf(w[base + 1] * 0.5f, &sb, &cb);
        __sincosf(w[base + 2] * 0.5f, &sc, &cc);
        float m00r = cb * ca, m00i = sb * sa;
        float m01r = -sb * ca, m01i = -cb * sa;
        float X = cc * m00r + sc * m00i;
        float Y = cc * m00i - sc * m00r;
        float Z = cc * m01r + sc * m01i;
        float Q = cc * m01i - sc * m01r;
        float ct = sqrtf(X * X + Y * Y);
        float st = sqrtf(Z * Z + Q * Q);
        float a = -atan2f(Y, X);
        float b = atan2f(Q, -Z);
        s_t[tid]  = st / fmaxf(ct, 1e-30f);
        s_ct[tid] = ct;  s_st[tid] = st;
        s_lam[tid] = a - b;
        s_phi[tid] = a + b;
    }
    __syncthreads();
    if (tid < 8) {
        float sn, cn;
        __sincosf(0.5f * s_lam[tid], &sn, &cn);
        s_W[tid] = make_float4(s_ct[tid] * cn, -s_ct[tid] * sn,   // A = ct e^{-i lam/2}
                               s_st[tid] * cn,  s_st[tid] * sn);  // B = st e^{+i lam/2}
    }
    if (tid == 8) {
        float C = 1.f;
#pragma unroll
        for (int g = 8; g < 32; g++) C *= s_ct[g];
        s_C2 = C * C;
    }
    // diag tables: 768 entries, 6 per thread
    {
        float2* s_diag2 = (float2*)s_diag4;
#pragma unroll
        for (int e = 0; e < 6; e++) {
            int n = tid * 6 + e;      // 0..767
            int j = n >> 8;           // table index 0..2 (= D_{j+1})
            int s = n & 255;
            float th = 0.f;
#pragma unroll
            for (int g = 0; g < 8; g++) {
                int g1 = 8 * (j + 1) + g;
                float sg1 = (__popc(c_rows[g1] & s) & 1) ? 1.f : -1.f;
                th += 0.5f * s_lam[g1] * sg1;
                int g0 = 8 * j + g;
                float sg0 = (__popc(c_rows[g0] & s) & 1) ? 1.f : -1.f;
                th += 0.5f * s_phi[g0] * sg0;
            }
            float sn, cn;
            __sincosf(th, &sn, &cn);
            int kk = s & 15, l4 = s >> 4;
            s_diag2[j * 256 + ((kk >> 1) * 16 + l4) * 2 + (kk & 1)] = make_float2(cn, sn);
        }
    }
    __syncthreads();

    // ---- main body ----
    int warp = (blockIdx.x * blockDim.x + threadIdx.x) >> 5;
    int lane = threadIdx.x & 31;
    if (warp >= W) return;
    int lane4 = lane & 15;
    int grp = lane >> 4;
    int gbase = lane & 16;

    // per-lane 1-qubit vector: v = W_q * (cos x/2, sin x/2)  (Enc+D0+L1)
    float xq = x[warp * 32 + lane];
    float sh, ch;
    __sincosf(0.5f * xq, &sh, &ch);
    float4 Wq = s_W[lane & 7];
    float v0r =  ch * Wq.x - sh * Wq.z;
    float v0i =  ch * Wq.y - sh * Wq.w;
    float v1r =  ch * Wq.z + sh * Wq.x;
    float v1i = -(ch * Wq.w + sh * Wq.y);

    // lane-part product L over qubits 0..3 (lane4 bit (3-q))
    ull Lr, Li;
#pragma unroll
    for (int qq = 0; qq < 4; qq++) {
        float a0r = __shfl_sync(FULL, v0r, gbase + qq);
        float a0i = __shfl_sync(FULL, v0i, gbase + qq);
        float a1r = __shfl_sync(FULL, v1r, gbase + qq);
        float a1i = __shfl_sync(FULL, v1i, gbase + qq);
        float b0r = __shfl_sync(FULL, v0r, gbase + 8 + qq);
        float b0i = __shfl_sync(FULL, v0i, gbase + 8 + qq);
        float b1r = __shfl_sync(FULL, v1r, gbase + 8 + qq);
        float b1i = __shfl_sync(FULL, v1i, gbase + 8 + qq);
        bool bit = (lane4 >> (3 - qq)) & 1;
        float srA = bit ? a1r : a0r;
        float siA = bit ? a1i : a0i;
        float srB = bit ? b1r : b0r;
        float siB = bit ? b1i : b0i;
        ull xr = pack2(srA, srB), xi = pack2(siA, siB), xin = pack2(-siA, -siB);
        if (qq == 0) { Lr = xr; Li = xi; }
        else {
            ull nLr, nLi;
            CMUL(nLr, nLi, Lr, Li, xr, xi, xin);
            Lr = nLr; Li = nLi;
        }
    }

    // product tree over qubits 4..7 (k bits 3..0), L folded in
    ull vr[16], vi[16];
    {
        ull Er[2], Ei[2];
        {
            ull q0r, q0i, q0in, q1r, q1i, q1in;
            FETCHQ(4, q0r, q0i, q0in, q1r, q1i, q1in);
            CMUL(Er[0], Ei[0], Lr, Li, q0r, q0i, q0in);
            CMUL(Er[1], Ei[1], Lr, Li, q1r, q1i, q1in);
        }
        ull Fr[4], Fi[4];
        {
            ull q0r, q0i, q0in, q1r, q1i, q1in;
            FETCHQ(5, q0r, q0i, q0in, q1r, q1i, q1in);
#pragma unroll
            for (int b = 0; b < 2; b++) {
                CMUL(Fr[2*b],   Fi[2*b],   Er[b], Ei[b], q0r, q0i, q0in);
                CMUL(Fr[2*b+1], Fi[2*b+1], Er[b], Ei[b], q1r, q1i, q1in);
            }
        }
        ull Gr[8], Gi[8];
        {
            ull q0r, q0i, q0in, q1r, q1i, q1in;
            FETCHQ(6, q0r, q0i, q0in, q1r, q1i, q1in);
#pragma unroll
            for (int b = 0; b < 4; b++) {
                CMUL(Gr[2*b],   Gi[2*b],   Fr[b], Fi[b], q0r, q0i, q0in);
                CMUL(Gr[2*b+1], Gi[2*b+1], Fr[b], Fi[b], q1r, q1i, q1in);
            }
        }
        {
            ull q0r, q0i, q0in, q1r, q1i, q1in;
            FETCHQ(7, q0r, q0i, q0in, q1r, q1i, q1in);
#pragma unroll
            for (int b = 0; b < 8; b++) {
                CMUL(vr[2*b],   vi[2*b],   Gr[b], Gi[b], q0r, q0i, q0in);
                CMUL(vr[2*b+1], vi[2*b+1], Gr[b], Gi[b], q1r, q1i, q1in);
            }
        }
    }

    applyD(vr, vi, lane4, s_diag4);
    // ---- layer 2 (cross/local interleaved; gates within a layer commute) ----
    rygate<0xC0, 0x80,  8>(vr, vi, lane4, s_t);
    rygate<0x0C, 0xF8, 12>(vr, vi, lane4, s_t);
    rygate<0x60, 0xC0,  9>(vr, vi, lane4, s_t);
    rygate<0x06, 0xFC, 13>(vr, vi, lane4, s_t);
    rygate<0x30, 0xE0, 10>(vr, vi, lane4, s_t);
    rygate<0x03, 0xFE, 14>(vr, vi, lane4, s_t);
    rygate<0x18, 0xF0, 11>(vr, vi, lane4, s_t);
    rygate<0x01, 0xFF, 15>(vr, vi, lane4, s_t);
    applyD(vr, vi, lane4, s_diag4 + 128);
    // ---- layer 3 ----
    rygate<0xA0, 0x80, 16>(vr, vi, lane4, s_t);
    rygate<0x0A, 0xA8, 20>(vr, vi, lane4, s_t);
    rygate<0x50, 0x40, 17>(vr, vi, lane4, s_t);
    rygate<0x05, 0x54, 21>(vr, vi, lane4, s_t);
    rygate<0x28, 0xA0, 18>(vr, vi, lane4, s_t);
    rygate<0x02, 0xAA, 22>(vr, vi, lane4, s_t);
    rygate<0x14, 0x50, 19>(vr, vi, lane4, s_t);
    rygate<0x01, 0x55, 23>(vr, vi, lane4, s_t);
    applyD(vr, vi, lane4, s_diag4 + 256);
    // ---- layer 4 (trailing diagonal dropped: |amp|^2 invariant) ----
    rygate<0xF0, 0x80, 24>(vr, vi, lane4, s_t);
    rygate<0x0F, 0x98, 28>(vr, vi, lane4, s_t);
    rygate<0x78, 0xC0, 25>(vr, vi, lane4, s_t);
    rygate<0x07, 0xCC, 29>(vr, vi, lane4, s_t);
    rygate<0x3C, 0x60, 26>(vr, vi, lane4, s_t);
    rygate<0x03, 0x66, 30>(vr, vi, lane4, s_t);
    rygate<0x1E, 0x30, 27>(vr, vi, lane4, s_t);
    rygate<0x01, 0x33, 31>(vr, vi, lane4, s_t);

    // ---- measurement: rows q0..q7 = 80,40,20,10,88,44,22,11; C^2 folded in ----
    float P0 = 0.f, S80 = 0.f, S40 = 0.f, S20 = 0.f, S10 = 0.f;
    float P1 = 0.f, S81 = 0.f, S41 = 0.f, S21 = 0.f, S11 = 0.f;
#pragma unroll
    for (int k = 0; k < 16; k++) {
        float r0 = lo32(vr[k]), i0 = lo32(vi[k]);
        float r1 = hi32(vr[k]), i1 = hi32(vi[k]);
        float p0 = r0 * r0 + i0 * i0;
        float p1 = r1 * r1 + i1 * i1;
        P0 += p0;                          P1 += p1;
        S80 += (k & 8) ? -p0 : p0;         S81 += (k & 8) ? -p1 : p1;
        S40 += (k & 4) ? -p0 : p0;         S41 += (k & 4) ? -p1 : p1;
        S20 += (k & 2) ? -p0 : p0;         S21 += (k & 2) ? -p1 : p1;
        S10 += (k & 1) ? -p0 : p0;         S11 += (k & 1) ? -p1 : p1;
    }
    float C2 = s_C2;
    float g8 = (lane4 & 8) ? -C2 : C2;
    float g4 = (lane4 & 4) ? -C2 : C2;
    float g2 = (lane4 & 2) ? -C2 : C2;
    float g1 = (lane4 & 1) ? -C2 : C2;
    float zz[16];
    zz[0]  = g8 * P0;   zz[1]  = g4 * P0;   zz[2]  = g2 * P0;   zz[3]  = g1 * P0;
    zz[4]  = g8 * S80;  zz[5]  = g4 * S40;  zz[6]  = g2 * S20;  zz[7]  = g1 * S10;
    zz[8]  = g8 * P1;   zz[9]  = g4 * P1;   zz[10] = g2 * P1;   zz[11] = g1 * P1;
    zz[12] = g8 * S81;  zz[13] = g4 * S41;  zz[14] = g2 * S21;  zz[15] = g1 * S11;

    // reduce-scatter: lane4 ends holding the full sum for output index lane4.
    // Each round: send the half I don't keep, keep-compact, add received.
    {
        bool hi = (lane4 & 8) != 0;
        float snd[8];
#pragma unroll
        for (int j = 0; j < 8; j++) snd[j] = hi ? zz[j] : zz[8 + j];
#pragma unroll
        for (int j = 0; j < 8; j++) {
            float rcv = __shfl_xor_sync(FULL, snd[j], 8);
            zz[j] = (hi ? zz[8 + j] : zz[j]) + rcv;
        }
    }
    {
        bool hi = (lane4 & 4) != 0;
        float snd[4];
#pragma unroll
        for (int j = 0; j < 4; j++) snd[j] = hi ? zz[j] : zz[4 + j];
#pragma unroll
        for (int j = 0; j < 4; j++) {
            float rcv = __shfl_xor_sync(FULL, snd[j], 4);
            zz[j] = (hi ? zz[4 + j] : zz[j]) + rcv;
        }
    }
    {
        bool hi = (lane4 & 2) != 0;
        float snd[2];
#pragma unroll
        for (int j = 0; j < 2; j++) snd[j] = hi ? zz[j] : zz[2 + j];
#pragma unroll
        for (int j = 0; j < 2; j++) {
            float rcv = __shfl_xor_sync(FULL, snd[j], 2);
            zz[j] = (hi ? zz[2 + j] : zz[j]) + rcv;
        }
    }
    {
        bool hi = (lane4 & 1) != 0;
        float snd = hi ? zz[0] : zz[1];
        float rcv = __shfl_xor_sync(FULL, snd, 1);
        zz[0] = (hi ? zz[1] : zz[0]) + rcv;
    }
    // fully coalesced: 32 consecutive floats per warp
    out[warp * 32 + grp * 16 + lane4] = zz[0];
}

extern "C" void kernel_launch(void* const* d_in, const int* in_sizes, int n_in,
                              void* d_out, int out_size) {
    const float* x = (const float*)d_in[0];
    const float* w = (const float*)d_in[1];
    float* out = (float*)d_out;
    int B = in_sizes[0] / 8;
    int W = B / 4;   // 4 samples per warp (16-lane groups, f32x2-packed pairs)

    int threads = 128;
    long long total = (long long)W * 32;
    int blocks = (int)((total + threads - 1) / threads);
    qsim<<<blocks, threads>>>(x, w, out, W);
}

// round 16
// speedup vs baseline: 2.1444x; 1.0889x over previous
#include <cuda_runtime.h>
#include <cuda_bf16.h>

#define FULL 0xFFFFFFFFu
typedef unsigned long long ull;

// Relabeled parity rows per gate (CNOTs folded; must match template R args)
__host__ __device__ constexpr int kRow(int g) {
    constexpr int rows[32] = {
        0x80,0x40,0x20,0x10,0x08,0x04,0x02,0x01,
        0x80,0xC0,0xE0,0xF0,0xF8,0xFC,0xFE,0xFF,
        0x80,0x40,0xA0,0x50,0xA8,0x54,0xAA,0x55,
        0x80,0xC0,0x60,0x30,0x98,0xCC,0x66,0x33
    };
    return rows[g];
}
// column mask: bit g set iff row_g contains state-bit b (compile-time)
__host__ __device__ constexpr unsigned colmask(int b) {
    unsigned m = 0;
    for (int g = 0; g < 32; g++)
        if ((kRow(g) >> b) & 1) m |= 1u << g;
    return m;
}

// ---- packed fp32x2 helpers: lanes = (sampleA, sampleB) ----
__device__ __forceinline__ ull fma2(ull a, ull b, ull c) {
    ull d; asm("fma.rn.f32x2 %0, %1, %2, %3;" : "=l"(d) : "l"(a), "l"(b), "l"(c));
    return d;
}
__device__ __forceinline__ ull mul2(ull a, ull b) {
    ull d; asm("mul.rn.f32x2 %0, %1, %2;" : "=l"(d) : "l"(a), "l"(b));
    return d;
}
__device__ __forceinline__ ull pack2(float lo, float hi) {
    ull d; asm("mov.b64 %0, {%1, %2};" : "=l"(d) : "f"(lo), "f"(hi));
    return d;
}
__device__ __forceinline__ float lo32(ull v) { return __uint_as_float((unsigned)v); }
__device__ __forceinline__ float hi32(ull v) { return __uint_as_float((unsigned)(v >> 32)); }

// packed complex multiply: (nr,ni) = (ar,ai)*(br,bi); bin = -bi packed
#define CMUL(nr, ni, ar, ai, br, bi, bin) \
    nr = fma2(ar, br, mul2(ai, bin));     \
    ni = fma2(ar, bi, mul2(ai, br));

// fetch qubit qq's full 2-vector for both samples of this group, packed
#define FETCHQ(qq, q0r, q0i, q0in, q1r, q1i, q1in) {                      \
    float a0r = __shfl_sync(FULL, v0r, gbase + (qq));                     \
    float a0i = __shfl_sync(FULL, v0i, gbase + (qq));                     \
    float a1r = __shfl_sync(FULL, v1r, gbase + (qq));                     \
    float a1i = __shfl_sync(FULL, v1i, gbase + (qq));                     \
    float b0r = __shfl_sync(FULL, v0r, gbase + 8 + (qq));                 \
    float b0i = __shfl_sync(FULL, v0i, gbase + 8 + (qq));                 \
    float b1r = __shfl_sync(FULL, v1r, gbase + 8 + (qq));                 \
    float b1i = __shfl_sync(FULL, v1i, gbase + 8 + (qq));                 \
    q0r = pack2(a0r, b0r); q0i = pack2(a0i, b0i); q0in = pack2(-a0i, -b0i); \
    q1r = pack2(a1r, b1r); q1i = pack2(a1i, b1i); q1in = pack2(-a1i, -b1i); }

// ---- fast-Givens Ry gate, 16-lane layout: lane4 = state bits 7..4, k = bits 3..0
// new[s] = a[s] + sigma(s)*t*a[s^M]; sigma = +1 if <R,s> odd. 0x6996 = 4-bit parity.
template<int M, int R, int G>
__device__ __forceinline__ void rygate(ull (&vr)[16], ull (&vi)[16], int lane4,
                                       const float* __restrict__ s_t) {
    const float tg = s_t[G];
    constexpr int ML = (M >> 4) & 15;
    constexpr int MK = M & 15;
    constexpr int RL = (R >> 4) & 15;
    constexpr int RK = R & 15;
    constexpr int HB = (MK >= 8) ? 8 : (MK >= 4) ? 4 : (MK >= 2) ? 2 : 1;

    int pl = (0x6996 >> (lane4 & RL)) & 1;
    float tA = pl ? tg : -tg;
    ull tP = pack2(tA, tA);
    ull tN = pack2(-tA, -tA);

    if constexpr (ML != 0 && MK == 0) {
#pragma unroll
        for (int k = 0; k < 16; k++) {
            ull br = __shfl_xor_sync(FULL, vr[k], ML);
            ull bi = __shfl_xor_sync(FULL, vi[k], ML);
            ull sk = ((0x6996 >> (RK & k)) & 1) ? tN : tP;
            vr[k] = fma2(sk, br, vr[k]);
            vi[k] = fma2(sk, bi, vi[k]);
        }
    } else if constexpr (ML != 0) {
        // mixed: pair-complete — all shuffles of pair (k, k^MK) before any write
#pragma unroll
        for (int k = 0; k < 16; k++) {
            if ((k & HB) == 0) {
                const int k2 = k ^ MK;
                ull pr = __shfl_xor_sync(FULL, vr[k2], ML);
                ull pi = __shfl_xor_sync(FULL, vi[k2], ML);
                ull qr = __shfl_xor_sync(FULL, vr[k],  ML);
                ull qi = __shfl_xor_sync(FULL, vi[k],  ML);
                ull s1 = ((0x6996 >> (RK & k )) & 1) ? tN : tP;
                ull s2 = ((0x6996 >> (RK & k2)) & 1) ? tN : tP;
                vr[k]  = fma2(s1, pr, vr[k]);
                vi[k]  = fma2(s1, pi, vi[k]);
                vr[k2] = fma2(s2, qr, vr[k2]);
                vi[k2] = fma2(s2, qi, vi[k2]);
            }
        }
    } else {
#pragma unroll
        for (int k = 0; k < 16; k++) {
            if ((k & HB) == 0) {
                const int k2 = k ^ MK;
                ull s1 = ((0x6996 >> (RK & k )) & 1) ? tN : tP;
                ull s2 = ((0x6996 >> (RK & k2)) & 1) ? tN : tP;
                ull tr = vr[k], ti = vi[k], ur = vr[k2], ui = vi[k2];
                vr[k]  = fma2(s1, ur, tr);
                vi[k]  = fma2(s1, ui, ti);
                vr[k2] = fma2(s2, tr, ur);
                vi[k2] = fma2(s2, ti, ui);
            }
        }
    }
}

// diag table transposed in smem: tbl[h*16 + lane4] = phases of slots
// (lane4*16 + 2h, lane4*16 + 2h + 1)  -> conflict-free 16-lane float4 reads
__device__ __forceinline__ void applyD(ull (&vr)[16], ull (&vi)[16], int lane4,
                                       const float4* __restrict__ tbl) {
#pragma unroll
    for (int h = 0; h < 8; h++) {
        float4 p = tbl[h * 16 + lane4];
        int k = 2 * h;
        {
            ull px = pack2(p.x, p.x), py = pack2(p.y, p.y), pyn = pack2(-p.y, -p.y);
            ull nr = fma2(px, vr[k], mul2(pyn, vi[k]));
            ull ni = fma2(px, vi[k], mul2(py,  vr[k]));
            vr[k] = nr; vi[k] = ni;
        }
        {
            ull px = pack2(p.z, p.z), py = pack2(p.w, p.w), pyn = pack2(-p.w, -p.w);
            ull nr = fma2(px, vr[k+1], mul2(pyn, vi[k+1]));
            ull ni = fma2(px, vi[k+1], mul2(py,  vr[k+1]));
            vr[k+1] = nr; vi[k+1] = ni;
        }
    }
}

__global__ void __launch_bounds__(128)
qsim(const float* __restrict__ x, const float* __restrict__ w,
     float* __restrict__ out, int W, int nChunks) {
    // ---- per-block inlined prep (identical in every block, deterministic) ----
    __shared__ float4 s_diag4[3 * 128];   // tables j=1..3, transposed
    __shared__ float  s_t[32];
    __shared__ float4 s_W[8];
    __shared__ float  s_C2;
    __shared__ float  s_lam2[32], s_phi2[32], s_ct[32], s_st[32];

    int tid = threadIdx.x;
    if (tid < 32) {
        int base = tid * 3;
        float sa, ca, sb, cb, sc, cc;
        __sincosf(w[base]     * 0.5f, &sa, &ca);
        __sincosf(w[base + 1] * 0.5f, &sb, &cb);
        __sincosf(w[base + 2] * 0.5f, &sc, &cc);
        float m00r = cb * ca, m00i = sb * sa;
        float m01r = -sb * ca, m01i = -cb * sa;
        float X = cc * m00r + sc * m00i;
        float Y = cc * m00i - sc * m00r;
        float Z = cc * m01r + sc * m01i;
        float Q = cc * m01i - sc * m01r;
        float ct = sqrtf(X * X + Y * Y);
        float st = sqrtf(Z * Z + Q * Q);
        float a = -atan2f(Y, X);
        float b = atan2f(Q, -Z);
        s_t[tid]  = st / fmaxf(ct, 1e-30f);
        s_ct[tid] = ct;  s_st[tid] = st;
        s_lam2[tid] = 0.5f * (a - b);   // stored pre-halved
        s_phi2[tid] = 0.5f * (a + b);
    }
    __syncthreads();
    if (tid < 8) {
        float sn, cn;
        __sincosf(s_lam2[tid], &sn, &cn);
        s_W[tid] = make_float4(s_ct[tid] * cn, -s_ct[tid] * sn,   // A = ct e^{-i lam/2}
                               s_st[tid] * cn,  s_st[tid] * sn);  // B = st e^{+i lam/2}
    }
    if (tid == 8) {
        float C = 1.f;
#pragma unroll
        for (int g = 8; g < 32; g++) C *= s_ct[g];
        s_C2 = C * C;
    }
    // diag tables: 2 slots per thread; all 32 gate-parities from 8 constexpr XORs
    {
        float2* s_diag2 = (float2*)s_diag4;
#pragma unroll
        for (int e = 0; e < 2; e++) {
            int s = tid * 2 + e;      // slot 0..255
            unsigned m = 0;
#pragma unroll
            for (int b = 0; b < 8; b++)
                if ((s >> b) & 1) m ^= colmask(b);
            int kk = s & 15, l4 = s >> 4;
            int sidx = ((kk >> 1) * 16 + l4) * 2 + (kk & 1);
#pragma unroll
            for (int j = 0; j < 3; j++) {
                float th = 0.f;
#pragma unroll
                for (int g = 0; g < 8; g++) {
                    int g1 = 8 * (j + 1) + g;
                    th += ((m >> g1) & 1) ? s_lam2[g1] : -s_lam2[g1];
                    int g0 = 8 * j + g;
                    th += ((m >> g0) & 1) ? s_phi2[g0] : -s_phi2[g0];
                }
                float sn, cn;
                __sincosf(th, &sn, &cn);
                s_diag2[j * 256 + sidx] = make_float2(cn, sn);
            }
        }
    }
    __syncthreads();

    // ---- persistent work loop: one wave of blocks, grid-stride over chunks ----
    int lane = threadIdx.x & 31;
    int wib  = threadIdx.x >> 5;        // warp in block
    int lane4 = lane & 15;
    int grp = lane >> 4;
    int gbase = lane & 16;
    const float4 Wq = s_W[lane & 7];
    const float C2 = s_C2;

    for (int chunk = blockIdx.x; chunk < nChunks; chunk += gridDim.x) {
        int warp = chunk * 4 + wib;
        if (warp >= W) continue;

        // per-lane 1-qubit vector: v = W_q * (cos x/2, sin x/2)  (Enc+D0+L1)
        float xq = x[warp * 32 + lane];
        float sh, ch;
        __sincosf(0.5f * xq, &sh, &ch);
        float v0r =  ch * Wq.x - sh * Wq.z;
        float v0i =  ch * Wq.y - sh * Wq.w;
        float v1r =  ch * Wq.z + sh * Wq.x;
        float v1i = -(ch * Wq.w + sh * Wq.y);

        // lane-part product L over qubits 0..3 (lane4 bit (3-q))
        ull Lr, Li;
#pragma unroll
        for (int qq = 0; qq < 4; qq++) {
            float a0r = __shfl_sync(FULL, v0r, gbase + qq);
            float a0i = __shfl_sync(FULL, v0i, gbase + qq);
            float a1r = __shfl_sync(FULL, v1r, gbase + qq);
            float a1i = __shfl_sync(FULL, v1i, gbase + qq);
            float b0r = __shfl_sync(FULL, v0r, gbase + 8 + qq);
            float b0i = __shfl_sync(FULL, v0i, gbase + 8 + qq);
            float b1r = __shfl_sync(FULL, v1r, gbase + 8 + qq);
            float b1i = __shfl_sync(FULL, v1i, gbase + 8 + qq);
            bool bit = (lane4 >> (3 - qq)) & 1;
            float srA = bit ? a1r : a0r;
            float siA = bit ? a1i : a0i;
            float srB = bit ? b1r : b0r;
            float siB = bit ? b1i : b0i;
            ull xr = pack2(srA, srB), xi = pack2(siA, siB), xin = pack2(-siA, -siB);
            if (qq == 0) { Lr = xr; Li = xi; }
            else {
                ull nLr, nLi;
                CMUL(nLr, nLi, Lr, Li, xr, xi, xin);
                Lr = nLr; Li = nLi;
            }
        }

        // product tree over qubits 4..7 (k bits 3..0), L folded in
        ull vr[16], vi[16];
        {
            ull Er[2], Ei[2];
            {
                ull q0r, q0i, q0in, q1r, q1i, q1in;
                FETCHQ(4, q0r, q0i, q0in, q1r, q1i, q1in);
                CMUL(Er[0], Ei[0], Lr, Li, q0r, q0i, q0in);
                CMUL(Er[1], Ei[1], Lr, Li, q1r, q1i, q1in);
            }
            ull Fr[4], Fi[4];
            {
                ull q0r, q0i, q0in, q1r, q1i, q1in;
                FETCHQ(5, q0r, q0i, q0in, q1r, q1i, q1in);
#pragma unroll
                for (int b = 0; b < 2; b++) {
                    CMUL(Fr[2*b],   Fi[2*b],   Er[b], Ei[b], q0r, q0i, q0in);
                    CMUL(Fr[2*b+1], Fi[2*b+1], Er[b], Ei[b], q1r, q1i, q1in);
                }
            }
            ull Gr[8], Gi[8];
            {
                ull q0r, q0i, q0in, q1r, q1i, q1in;
                FETCHQ(6, q0r, q0i, q0in, q1r, q1i, q1in);
#pragma unroll
                for (int b = 0; b < 4; b++) {
                    CMUL(Gr[2*b],   Gi[2*b],   Fr[b], Fi[b], q0r, q0i, q0in);
                    CMUL(Gr[2*b+1], Gi[2*b+1], Fr[b], Fi[b], q1r, q1i, q1in);
                }
            }
            {
                ull q0r, q0i, q0in, q1r, q1i, q1in;
                FETCHQ(7, q0r, q0i, q0in, q1r, q1i, q1in);
#pragma unroll
                for (int b = 0; b < 8; b++) {
                    CMUL(vr[2*b],   vi[2*b],   Gr[b], Gi[b], q0r, q0i, q0in);
                    CMUL(vr[2*b+1], vi[2*b+1], Gr[b], Gi[b], q1r, q1i, q1in);
                }
            }
        }

        applyD(vr, vi, lane4, s_diag4);
        // ---- layer 2 (cross/local interleaved; gates within a layer commute) ----
        rygate<0xC0, 0x80,  8>(vr, vi, lane4, s_t);
        rygate<0x0C, 0xF8, 12>(vr, vi, lane4, s_t);
        rygate<0x60, 0xC0,  9>(vr, vi, lane4, s_t);
        rygate<0x06, 0xFC, 13>(vr, vi, lane4, s_t);
        rygate<0x30, 0xE0, 10>(vr, vi, lane4, s_t);
        rygate<0x03, 0xFE, 14>(vr, vi, lane4, s_t);
        rygate<0x18, 0xF0, 11>(vr, vi, lane4, s_t);
        rygate<0x01, 0xFF, 15>(vr, vi, lane4, s_t);
        applyD(vr, vi, lane4, s_diag4 + 128);
        // ---- layer 3 ----
        rygate<0xA0, 0x80, 16>(vr, vi, lane4, s_t);
        rygate<0x0A, 0xA8, 20>(vr, vi, lane4, s_t);
        rygate<0x50, 0x40, 17>(vr, vi, lane4, s_t);
        rygate<0x05, 0x54, 21>(vr, vi, lane4, s_t);
        rygate<0x28, 0xA0, 18>(vr, vi, lane4, s_t);
        rygate<0x02, 0xAA, 22>(vr, vi, lane4, s_t);
        rygate<0x14, 0x50, 19>(vr, vi, lane4, s_t);
        rygate<0x01, 0x55, 23>(vr, vi, lane4, s_t);
        applyD(vr, vi, lane4, s_diag4 + 256);
        // ---- layer 4 (trailing diagonal dropped: |amp|^2 invariant) ----
        rygate<0xF0, 0x80, 24>(vr, vi, lane4, s_t);
        rygate<0x0F, 0x98, 28>(vr, vi, lane4, s_t);
        rygate<0x78, 0xC0, 25>(vr, vi, lane4, s_t);
        rygate<0x07, 0xCC, 29>(vr, vi, lane4, s_t);
        rygate<0x3C, 0x60, 26>(vr, vi, lane4, s_t);
        rygate<0x03, 0x66, 30>(vr, vi, lane4, s_t);
        rygate<0x1E, 0x30, 27>(vr, vi, lane4, s_t);
        rygate<0x01, 0x33, 31>(vr, vi, lane4, s_t);

        // ---- measurement: rows q0..q7 = 80,40,20,10,88,44,22,11; C^2 folded in ----
        float P0 = 0.f, S80 = 0.f, S40 = 0.f, S20 = 0.f, S10 = 0.f;
        float P1 = 0.f, S81 = 0.f, S41 = 0.f, S21 = 0.f, S11 = 0.f;
#pragma unroll
        for (int k = 0; k < 16; k++) {
            float r0 = lo32(vr[k]), i0 = lo32(vi[k]);
            float r1 = hi32(vr[k]), i1 = hi32(vi[k]);
            float p0 = r0 * r0 + i0 * i0;
            float p1 = r1 * r1 + i1 * i1;
            P0 += p0;                          P1 += p1;
            S80 += (k & 8) ? -p0 : p0;         S81 += (k & 8) ? -p1 : p1;
            S40 += (k & 4) ? -p0 : p0;         S41 += (k & 4) ? -p1 : p1;
            S20 += (k & 2) ? -p0 : p0;         S21 += (k & 2) ? -p1 : p1;
            S10 += (k & 1) ? -p0 : p0;         S11 += (k & 1) ? -p1 : p1;
        }
        float g8 = (lane4 & 8) ? -C2 : C2;
        float g4 = (lane4 & 4) ? -C2 : C2;
        float g2 = (lane4 & 2) ? -C2 : C2;
        float g1 = (lane4 & 1) ? -C2 : C2;
        float zz[16];
        zz[0]  = g8 * P0;   zz[1]  = g4 * P0;   zz[2]  = g2 * P0;   zz[3]  = g1 * P0;
        zz[4]  = g8 * S80;  zz[5]  = g4 * S40;  zz[6]  = g2 * S20;  zz[7]  = g1 * S10;
        zz[8]  = g8 * P1;   zz[9]  = g4 * P1;   zz[10] = g2 * P1;   zz[11] = g1 * P1;
        zz[12] = g8 * S81;  zz[13] = g4 * S41;  zz[14] = g2 * S21;  zz[15] = g1 * S11;

        // reduce-scatter: lane4 ends holding the full sum for output index lane4.
        {
            bool hi = (lane4 & 8) != 0;
            float snd[8];
#pragma unroll
            for (int j = 0; j < 8; j++) snd[j] = hi ? zz[j] : zz[8 + j];
#pragma unroll
            for (int j = 0; j < 8; j++) {
                float rcv = __shfl_xor_sync(FULL, snd[j], 8);
                zz[j] = (hi ? zz[8 + j] : zz[j]) + rcv;
            }
        }
        {
            bool hi = (lane4 & 4) != 0;
            float snd[4];
#pragma unroll
            for (int j = 0; j < 4; j++) snd[j] = hi ? zz[j] : zz[4 + j];
#pragma unroll
            for (int j = 0; j < 4; j++) {
                float rcv = __shfl_xor_sync(FULL, snd[j], 4);
                zz[j] = (hi ? zz[4 + j] : zz[j]) + rcv;
            }
        }
        {
            bool hi = (lane4 & 2) != 0;
            float snd[2];
#pragma unroll
            for (int j = 0; j < 2; j++) snd[j] = hi ? zz[j] : zz[2 + j];
#pragma unroll
            for (int j = 0; j < 2; j++) {
                float rcv = __shfl_xor_sync(FULL, snd[j], 2);
                zz[j] = (hi ? zz[2 + j] : zz[j]) + rcv;
            }
        }
        {
            bool hi = (lane4 & 1) != 0;
            float snd = hi ? zz[0] : zz[1];
            float rcv = __shfl_xor_sync(FULL, snd, 1);
            zz[0] = (hi ? zz[1] : zz[0]) + rcv;
        }
        // fully coalesced: 32 consecutive floats per warp
        out[warp * 32 + grp * 16 + lane4] = zz[0];
    }
}

extern "C" void kernel_launch(void* const* d_in, const int* in_sizes, int n_in,
                              void* d_out, int out_size) {
    const float* x = (const float*)d_in[0];
    const float* w = (const float*)d_in[1];
    float* out = (float*)d_out;
    int B = in_sizes[0] / 8;
    int W = B / 4;                       // 4 samples per warp
    int nChunks = (W + 3) >> 2;          // 4 warps per chunk

    // one wave: 5 blocks/SM (regs=94) x 148 SMs
    int blocks = nChunks < 740 ? nChunks : 740;
    qsim<<<blocks, 128>>>(x, w, out, W, nChunks);
}

// round 17
// speedup vs baseline: 2.1474x; 1.0014x over previous
#include <cuda_runtime.h>
#include <cuda_bf16.h>

#define FULL 0xFFFFFFFFu
typedef unsigned long long ull;

// Relabeled parity rows per gate (CNOTs folded; must match template R args)
__host__ __device__ constexpr int kRow(int g) {
    constexpr int rows[32] = {
        0x80,0x40,0x20,0x10,0x08,0x04,0x02,0x01,
        0x80,0xC0,0xE0,0xF0,0xF8,0xFC,0xFE,0xFF,
        0x80,0x40,0xA0,0x50,0xA8,0x54,0xAA,0x55,
        0x80,0xC0,0x60,0x30,0x98,0xCC,0x66,0x33
    };
    return rows[g];
}
// column mask: bit g set iff row_g contains state-bit b (compile-time)
__host__ __device__ constexpr unsigned colmask(int b) {
    unsigned m = 0;
    for (int g = 0; g < 32; g++)
        if ((kRow(g) >> b) & 1) m |= 1u << g;
    return m;
}

// ---- packed fp32x2 helpers: lanes = (sampleA, sampleB) ----
__device__ __forceinline__ ull fma2(ull a, ull b, ull c) {
    ull d; asm("fma.rn.f32x2 %0, %1, %2, %3;" : "=l"(d) : "l"(a), "l"(b), "l"(c));
    return d;
}
__device__ __forceinline__ ull mul2(ull a, ull b) {
    ull d; asm("mul.rn.f32x2 %0, %1, %2;" : "=l"(d) : "l"(a), "l"(b));
    return d;
}
__device__ __forceinline__ ull pack2(float lo, float hi) {
    ull d; asm("mov.b64 %0, {%1, %2};" : "=l"(d) : "f"(lo), "f"(hi));
    return d;
}
__device__ __forceinline__ float lo32(ull v) { return __uint_as_float((unsigned)v); }
__device__ __forceinline__ float hi32(ull v) { return __uint_as_float((unsigned)(v >> 32)); }

// packed complex multiply: (nr,ni) = (ar,ai)*(br,bi); bin = -bi packed
#define CMUL(nr, ni, ar, ai, br, bi, bin) \
    nr = fma2(ar, br, mul2(ai, bin));     \
    ni = fma2(ar, bi, mul2(ai, br));

// fetch qubit qq's full 2-vector for both samples of this group, packed
#define FETCHQ(qq, q0r, q0i, q0in, q1r, q1i, q1in) {                      \
    float a0r = __shfl_sync(FULL, v0r, gbase + (qq));                     \
    float a0i = __shfl_sync(FULL, v0i, gbase + (qq));                     \
    float a1r = __shfl_sync(FULL, v1r, gbase + (qq));                     \
    float a1i = __shfl_sync(FULL, v1i, gbase + (qq));                     \
    float b0r = __shfl_sync(FULL, v0r, gbase + 8 + (qq));                 \
    float b0i = __shfl_sync(FULL, v0i, gbase + 8 + (qq));                 \
    float b1r = __shfl_sync(FULL, v1r, gbase + 8 + (qq));                 \
    float b1i = __shfl_sync(FULL, v1i, gbase + 8 + (qq));                 \
    q0r = pack2(a0r, b0r); q0i = pack2(a0i, b0i); q0in = pack2(-a0i, -b0i); \
    q1r = pack2(a1r, b1r); q1i = pack2(a1i, b1i); q1in = pack2(-a1i, -b1i); }

// ---- fast-Givens Ry gate, 16-lane layout: lane4 = state bits 7..4, k = bits 3..0
// new[s] = a[s] + sigma(s)*t*a[s^M]; sigma = +1 if <R,s> odd. 0x6996 = 4-bit parity.
template<int M, int R, int G>
__device__ __forceinline__ void rygate(ull (&vr)[16], ull (&vi)[16], int lane4,
                                       const float* __restrict__ s_t) {
    const float tg = s_t[G];
    constexpr int ML = (M >> 4) & 15;
    constexpr int MK = M & 15;
    constexpr int RL = (R >> 4) & 15;
    constexpr int RK = R & 15;
    constexpr int HB = (MK >= 8) ? 8 : (MK >= 4) ? 4 : (MK >= 2) ? 2 : 1;

    int pl = (0x6996 >> (lane4 & RL)) & 1;
    float tA = pl ? tg : -tg;
    ull tP = pack2(tA, tA);
    ull tN = pack2(-tA, -tA);

    if constexpr (ML != 0 && MK == 0) {
#pragma unroll
        for (int k = 0; k < 16; k++) {
            ull br = __shfl_xor_sync(FULL, vr[k], ML);
            ull bi = __shfl_xor_sync(FULL, vi[k], ML);
            ull sk = ((0x6996 >> (RK & k)) & 1) ? tN : tP;
            vr[k] = fma2(sk, br, vr[k]);
            vi[k] = fma2(sk, bi, vi[k]);
        }
    } else if constexpr (ML != 0) {
        // mixed: pair-complete — all shuffles of pair (k, k^MK) before any write
#pragma unroll
        for (int k = 0; k < 16; k++) {
            if ((k & HB) == 0) {
                const int k2 = k ^ MK;
                ull pr = __shfl_xor_sync(FULL, vr[k2], ML);
                ull pi = __shfl_xor_sync(FULL, vi[k2], ML);
                ull qr = __shfl_xor_sync(FULL, vr[k],  ML);
                ull qi = __shfl_xor_sync(FULL, vi[k],  ML);
                ull s1 = ((0x6996 >> (RK & k )) & 1) ? tN : tP;
                ull s2 = ((0x6996 >> (RK & k2)) & 1) ? tN : tP;
                vr[k]  = fma2(s1, pr, vr[k]);
                vi[k]  = fma2(s1, pi, vi[k]);
                vr[k2] = fma2(s2, qr, vr[k2]);
                vi[k2] = fma2(s2, qi, vi[k2]);
            }
        }
    } else {
#pragma unroll
        for (int k = 0; k < 16; k++) {
            if ((k & HB) == 0) {
                const int k2 = k ^ MK;
                ull s1 = ((0x6996 >> (RK & k )) & 1) ? tN : tP;
                ull s2 = ((0x6996 >> (RK & k2)) & 1) ? tN : tP;
                ull tr = vr[k], ti = vi[k], ur = vr[k2], ui = vi[k2];
                vr[k]  = fma2(s1, ur, tr);
                vi[k]  = fma2(s1, ui, ti);
                vr[k2] = fma2(s2, tr, ur);
                vi[k2] = fma2(s2, ti, ui);
            }
        }
    }
}

// diag table transposed in smem: tbl[h*16 + lane4] = phases of slots
// (lane4*16 + 2h, lane4*16 + 2h + 1)  -> conflict-free 16-lane float4 reads
__device__ __forceinline__ void applyD(ull (&vr)[16], ull (&vi)[16], int lane4,
                                       const float4* __restrict__ tbl) {
#pragma unroll
    for (int h = 0; h < 8; h++) {
        float4 p = tbl[h * 16 + lane4];
        int k = 2 * h;
        {
            ull px = pack2(p.x, p.x), py = pack2(p.y, p.y), pyn = pack2(-p.y, -p.y);
            ull nr = fma2(px, vr[k], mul2(pyn, vi[k]));
            ull ni = fma2(px, vi[k], mul2(py,  vr[k]));
            vr[k] = nr; vi[k] = ni;
        }
        {
            ull px = pack2(p.z, p.z), py = pack2(p.w, p.w), pyn = pack2(-p.w, -p.w);
            ull nr = fma2(px, vr[k+1], mul2(pyn, vi[k+1]));
            ull ni = fma2(px, vi[k+1], mul2(py,  vr[k+1]));
            vr[k+1] = nr; vi[k+1] = ni;
        }
    }
}

__global__ void __launch_bounds__(128)
qsim(const float* __restrict__ x, const float* __restrict__ w,
     float* __restrict__ out, int W, int nChunks) {
    // ---- per-block inlined prep (identical in every block, deterministic) ----
    __shared__ float4 s_diag4[3 * 128];   // tables j=1..3, transposed
    __shared__ float  s_t[32];
    __shared__ float4 s_W[8];
    __shared__ float  s_C2;
    __shared__ float  s_lam2[32], s_phi2[32], s_ct[32], s_st[32];

    int tid = threadIdx.x;
    if (tid < 32) {
        int base = tid * 3;
        float sa, ca, sb, cb, sc, cc;
        __sincosf(w[base]     * 0.5f, &sa, &ca);
        __sincosf(w[base + 1] * 0.5f, &sb, &cb);
        __sincosf(w[base + 2] * 0.5f, &sc, &cc);
        float m00r = cb * ca, m00i = sb * sa;
        float m01r = -sb * ca, m01i = -cb * sa;
        float X = cc * m00r + sc * m00i;
        float Y = cc * m00i - sc * m00r;
        float Z = cc * m01r + sc * m01i;
        float Q = cc * m01i - sc * m01r;
        float ct = sqrtf(X * X + Y * Y);
        float st = sqrtf(Z * Z + Q * Q);
        float a = -atan2f(Y, X);
        float b = atan2f(Q, -Z);
        s_t[tid]  = st / fmaxf(ct, 1e-30f);
        s_ct[tid] = ct;  s_st[tid] = st;
        s_lam2[tid] = 0.5f * (a - b);   // stored pre-halved
        s_phi2[tid] = 0.5f * (a + b);
    }
    __syncthreads();
    if (tid < 8) {
        float sn, cn;
        __sincosf(s_lam2[tid], &sn, &cn);
        s_W[tid] = make_float4(s_ct[tid] * cn, -s_ct[tid] * sn,   // A = ct e^{-i lam/2}
                               s_st[tid] * cn,  s_st[tid] * sn);  // B = st e^{+i lam/2}
    }
    if (tid == 8) {
        float C = 1.f;
#pragma unroll
        for (int g = 8; g < 32; g++) C *= s_ct[g];
        s_C2 = C * C;
    }
    // diag tables: 2 slots per thread; all 32 gate-parities from 8 constexpr XORs
    {
        float2* s_diag2 = (float2*)s_diag4;
#pragma unroll
        for (int e = 0; e < 2; e++) {
            int s = tid * 2 + e;      // slot 0..255
            unsigned m = 0;
#pragma unroll
            for (int b = 0; b < 8; b++)
                if ((s >> b) & 1) m ^= colmask(b);
            int kk = s & 15, l4 = s >> 4;
            int sidx = ((kk >> 1) * 16 + l4) * 2 + (kk & 1);
#pragma unroll
            for (int j = 0; j < 3; j++) {
                float th = 0.f;
#pragma unroll
                for (int g = 0; g < 8; g++) {
                    int g1 = 8 * (j + 1) + g;
                    th += ((m >> g1) & 1) ? s_lam2[g1] : -s_lam2[g1];
                    int g0 = 8 * j + g;
                    th += ((m >> g0) & 1) ? s_phi2[g0] : -s_phi2[g0];
                }
                float sn, cn;
                __sincosf(th, &sn, &cn);
                s_diag2[j * 256 + sidx] = make_float2(cn, sn);
            }
        }
    }
    __syncthreads();

    // ---- persistent work loop: one wave of blocks, grid-stride over chunks ----
    int lane = threadIdx.x & 31;
    int wib  = threadIdx.x >> 5;        // warp in block
    int lane4 = lane & 15;
    int grp = lane >> 4;
    int gbase = lane & 16;
    const float4 Wq = s_W[lane & 7];
    const float C2 = s_C2;

    for (int chunk = blockIdx.x; chunk < nChunks; chunk += gridDim.x) {
        int warp = chunk * 4 + wib;
        if (warp >= W) continue;

        // per-lane 1-qubit vector: v = W_q * (cos x/2, sin x/2)  (Enc+D0+L1)
        float xq = x[warp * 32 + lane];
        float sh, ch;
        __sincosf(0.5f * xq, &sh, &ch);
        float v0r =  ch * Wq.x - sh * Wq.z;
        float v0i =  ch * Wq.y - sh * Wq.w;
        float v1r =  ch * Wq.z + sh * Wq.x;
        float v1i = -(ch * Wq.w + sh * Wq.y);

        // lane-part product L over qubits 0..3 (lane4 bit (3-q))
        ull Lr, Li;
#pragma unroll
        for (int qq = 0; qq < 4; qq++) {
            float a0r = __shfl_sync(FULL, v0r, gbase + qq);
            float a0i = __shfl_sync(FULL, v0i, gbase + qq);
            float a1r = __shfl_sync(FULL, v1r, gbase + qq);
            float a1i = __shfl_sync(FULL, v1i, gbase + qq);
            float b0r = __shfl_sync(FULL, v0r, gbase + 8 + qq);
            float b0i = __shfl_sync(FULL, v0i, gbase + 8 + qq);
            float b1r = __shfl_sync(FULL, v1r, gbase + 8 + qq);
            float b1i = __shfl_sync(FULL, v1i, gbase + 8 + qq);
            bool bit = (lane4 >> (3 - qq)) & 1;
            float srA = bit ? a1r : a0r;
            float siA = bit ? a1i : a0i;
            float srB = bit ? b1r : b0r;
            float siB = bit ? b1i : b0i;
            ull xr = pack2(srA, srB), xi = pack2(siA, siB), xin = pack2(-siA, -siB);
            if (qq == 0) { Lr = xr; Li = xi; }
            else {
                ull nLr, nLi;
                CMUL(nLr, nLi, Lr, Li, xr, xi, xin);
                Lr = nLr; Li = nLi;
            }
        }

        // product tree over qubits 4..7 (k bits 3..0), L folded in
        ull vr[16], vi[16];
        {
            ull Er[2], Ei[2];
            {
                ull q0r, q0i, q0in, q1r, q1i, q1in;
                FETCHQ(4, q0r, q0i, q0in, q1r, q1i, q1in);
                CMUL(Er[0], Ei[0], Lr, Li, q0r, q0i, q0in);
                CMUL(Er[1], Ei[1], Lr, Li, q1r, q1i, q1in);
            }
            ull Fr[4], Fi[4];
            {
                ull q0r, q0i, q0in, q1r, q1i, q1in;
                FETCHQ(5, q0r, q0i, q0in, q1r, q1i, q1in);
#pragma unroll
                for (int b = 0; b < 2; b++) {
                    CMUL(Fr[2*b],   Fi[2*b],   Er[b], Ei[b], q0r, q0i, q0in);
                    CMUL(Fr[2*b+1], Fi[2*b+1], Er[b], Ei[b], q1r, q1i, q1in);
                }
            }
            ull Gr[8], Gi[8];
            {
                ull q0r, q0i, q0in, q1r, q1i, q1in;
                FETCHQ(6, q0r, q0i, q0in, q1r, q1i, q1in);
#pragma unroll
                for (int b = 0; b < 4; b++) {
                    CMUL(Gr[2*b],   Gi[2*b],   Fr[b], Fi[b], q0r, q0i, q0in);
                    CMUL(Gr[2*b+1], Gi[2*b+1], Fr[b], Fi[b], q1r, q1i, q1in);
                }
            }
            {
                ull q0r, q0i, q0in, q1r, q1i, q1in;
                FETCHQ(7, q0r, q0i, q0in, q1r, q1i, q1in);
#pragma unroll
                for (int b = 0; b < 8; b++) {
                    CMUL(vr[2*b],   vi[2*b],   Gr[b], Gi[b], q0r, q0i, q0in);
                    CMUL(vr[2*b+1], vi[2*b+1], Gr[b], Gi[b], q1r, q1i, q1in);
                }
            }
        }

        applyD(vr, vi, lane4, s_diag4);
        // ---- layer 2 (cross/local interleaved; gates within a layer commute) ----
        rygate<0xC0, 0x80,  8>(vr, vi, lane4, s_t);
        rygate<0x0C, 0xF8, 12>(vr, vi, lane4, s_t);
        rygate<0x60, 0xC0,  9>(vr, vi, lane4, s_t);
        rygate<0x06, 0xFC, 13>(vr, vi, lane4, s_t);
        rygate<0x30, 0xE0, 10>(vr, vi, lane4, s_t);
        rygate<0x03, 0xFE, 14>(vr, vi, lane4, s_t);
        rygate<0x18, 0xF0, 11>(vr, vi, lane4, s_t);
        rygate<0x01, 0xFF, 15>(vr, vi, lane4, s_t);
        applyD(vr, vi, lane4, s_diag4 + 128);
        // ---- layer 3 ----
        rygate<0xA0, 0x80, 16>(vr, vi, lane4, s_t);
        rygate<0x0A, 0xA8, 20>(vr, vi, lane4, s_t);
        rygate<0x50, 0x40, 17>(vr, vi, lane4, s_t);
        rygate<0x05, 0x54, 21>(vr, vi, lane4, s_t);
        rygate<0x28, 0xA0, 18>(vr, vi, lane4, s_t);
        rygate<0x02, 0xAA, 22>(vr, vi, lane4, s_t);
        rygate<0x14, 0x50, 19>(vr, vi, lane4, s_t);
        rygate<0x01, 0x55, 23>(vr, vi, lane4, s_t);
        applyD(vr, vi, lane4, s_diag4 + 256);
        // ---- layer 4 (trailing diagonal dropped: |amp|^2 invariant) ----
        rygate<0xF0, 0x80, 24>(vr, vi, lane4, s_t);
        rygate<0x0F, 0x98, 28>(vr, vi, lane4, s_t);
        rygate<0x78, 0xC0, 25>(vr, vi, lane4, s_t);
        rygate<0x07, 0xCC, 29>(vr, vi, lane4, s_t);
        rygate<0x3C, 0x60, 26>(vr, vi, lane4, s_t);
        rygate<0x03, 0x66, 30>(vr, vi, lane4, s_t);
        rygate<0x1E, 0x30, 27>(vr, vi, lane4, s_t);
        rygate<0x01, 0x33, 31>(vr, vi, lane4, s_t);

        // ---- measurement: rows q0..q7 = 80,40,20,10,88,44,22,11; C^2 folded in ----
        float P0 = 0.f, S80 = 0.f, S40 = 0.f, S20 = 0.f, S10 = 0.f;
        float P1 = 0.f, S81 = 0.f, S41 = 0.f, S21 = 0.f, S11 = 0.f;
#pragma unroll
        for (int k = 0; k < 16; k++) {
            float r0 = lo32(vr[k]), i0 = lo32(vi[k]);
            float r1 = hi32(vr[k]), i1 = hi32(vi[k]);
            float p0 = r0 * r0 + i0 * i0;
            float p1 = r1 * r1 + i1 * i1;
            P0 += p0;                          P1 += p1;
            S80 += (k & 8) ? -p0 : p0;         S81 += (k & 8) ? -p1 : p1;
            S40 += (k & 4) ? -p0 : p0;         S41 += (k & 4) ? -p1 : p1;
            S20 += (k & 2) ? -p0 : p0;         S21 += (k & 2) ? -p1 : p1;
            S10 += (k & 1) ? -p0 : p0;         S11 += (k & 1) ? -p1 : p1;
        }
        float g8 = (lane4 & 8) ? -C2 : C2;
        float g4 = (lane4 & 4) ? -C2 : C2;
        float g2 = (lane4 & 2) ? -C2 : C2;
        float g1 = (lane4 & 1) ? -C2 : C2;
        float zz[16];
        zz[0]  = g8 * P0;   zz[1]  = g4 * P0;   zz[2]  = g2 * P0;   zz[3]  = g1 * P0;
        zz[4]  = g8 * S80;  zz[5]  = g4 * S40;  zz[6]  = g2 * S20;  zz[7]  = g1 * S10;
        zz[8]  = g8 * P1;   zz[9]  = g4 * P1;   zz[10] = g2 * P1;   zz[11] = g1 * P1;
        zz[12] = g8 * S81;  zz[13] = g4 * S41;  zz[14] = g2 * S21;  zz[15] = g1 * S11;

        // reduce-scatter: lane4 ends holding the full sum for output index lane4.
        {
            bool hi = (lane4 & 8) != 0;
            float snd[8];
#pragma unroll
            for (int j = 0; j < 8; j++) snd[j] = hi ? zz[j] : zz[8 + j];
#pragma unroll
            for (int j = 0; j < 8; j++) {
                float rcv = __shfl_xor_sync(FULL, snd[j], 8);
                zz[j] = (hi ? zz[8 + j] : zz[j]) + rcv;
            }
        }
        {
            bool hi = (lane4 & 4) != 0;
            float snd[4];
#pragma unroll
            for (int j = 0; j < 4; j++) snd[j] = hi ? zz[j] : zz[4 + j];
#pragma unroll
            for (int j = 0; j < 4; j++) {
                float rcv = __shfl_xor_sync(FULL, snd[j], 4);
                zz[j] = (hi ? zz[4 + j] : zz[j]) + rcv;
            }
        }
        {
            bool hi = (lane4 & 2) != 0;
            float snd[2];
#pragma unroll
            for (int j = 0; j < 2; j++) snd[j] = hi ? zz[j] : zz[2 + j];
#pragma unroll
            for (int j = 0; j < 2; j++) {
                float rcv = __shfl_xor_sync(FULL, snd[j], 2);
                zz[j] = (hi ? zz[2 + j] : zz[j]) + rcv;
            }
        }
        {
            bool hi = (lane4 & 1) != 0;
            float snd = hi ? zz[0] : zz[1];
            float rcv = __shfl_xor_sync(FULL, snd, 1);
            zz[0] = (hi ? zz[1] : zz[0]) + rcv;
        }
        // fully coalesced: 32 consecutive floats per warp
        out[warp * 32 + grp * 16 + lane4] = zz[0];
    }
}

extern "C" void kernel_launch(void* const* d_in, const int* in_sizes, int n_in,
                              void* d_out, int out_size) {
    const float* x = (const float*)d_in[0];
    const float* w = (const float*)d_in[1];
    float* out = (float*)d_out;
    int B = in_sizes[0] / 8;
    int W = B / 4;                       // 4 samples per warp
    int nChunks = (W + 3) >> 2;          // 4 warps per chunk

    // one wave: 5 blocks/SM (regs=94) x 148 SMs
    int blocks = nChunks < 740 ? nChunks : 740;
    qsim<<<blocks, 128>>>(x, w, out, W, nChunks);
}